// round 1
// baseline (speedup 1.0000x reference)
#include <cuda_runtime.h>
#include <math_constants.h>

// Problem constants
#define PB 16      // batch
#define PN 256     // atoms
#define PD 1024    // model dim
#define PH 16      // heads
#define PDK 64     // head dim
#define GM (PB*PN) // 4096 gemm rows
#define GN PD      // 1024
#define GK PD      // 1024

#define LAM_ATT 0.33f
#define LAM_DIST 0.33f
// computed as in python: 1.0 - 0.33 - 0.33
__device__ __constant__ float LAM_ADJ_C = (float)(1.0 - 0.33 - 0.33);

// ---------------- scratch (device globals; no cudaMalloc allowed) ----------
__device__ float g_q[PB*PH*PN*PDK];   // [b][h][n][dk]
__device__ float g_k[PB*PH*PN*PDK];
__device__ float g_v[PB*PH*PN*PDK];
__device__ float g_x[PB*PN*PD];       // attention output, [b][n][d]
__device__ float g_pd[PB*PN*PN];      // LAM_DIST*p_dist + LAM_ADJ*p_adj

// ---------------------------------------------------------------------------
// SGEMM: C[4096x1024] = A[4096x1024] @ W[1024x1024] + bias
// BM=BN=128, BK=16, 256 threads, 8x8 microtile.
// out_mode 0: row-major [m][n];  out_mode 1: head-split to [b][h][n][dk]
// ---------------------------------------------------------------------------
__device__ __forceinline__ void sgemm_body(
    const float* __restrict__ A, const float* __restrict__ W,
    const float* __restrict__ bias, float* __restrict__ C, int out_mode)
{
    __shared__ float As[16][128];
    __shared__ float Bs[16][128];

    const int tid = threadIdx.x;
    const int tx = tid & 15;       // 0..15 (cols)
    const int ty = tid >> 4;       // 0..15 (rows)
    const int row0 = blockIdx.y * 128;
    const int col0 = blockIdx.x * 128;

    const int arow = tid >> 2;            // 0..63
    const int acol = (tid & 3) << 2;      // 0,4,8,12
    const int brow = tid >> 5;            // 0..7
    const int bcol = (tid & 31) << 2;     // 0..124

    float acc[8][8];
#pragma unroll
    for (int i = 0; i < 8; i++)
#pragma unroll
        for (int j = 0; j < 8; j++) acc[i][j] = 0.f;

    for (int kt = 0; kt < GK; kt += 16) {
#pragma unroll
        for (int p = 0; p < 2; p++) {
            float4 a = *(const float4*)(A + (size_t)(row0 + arow + p*64)*GK + kt + acol);
            As[acol+0][arow + p*64] = a.x;
            As[acol+1][arow + p*64] = a.y;
            As[acol+2][arow + p*64] = a.z;
            As[acol+3][arow + p*64] = a.w;
        }
#pragma unroll
        for (int p = 0; p < 2; p++) {
            *(float4*)&Bs[brow + p*8][bcol] =
                *(const float4*)(W + (size_t)(kt + brow + p*8)*GN + col0 + bcol);
        }
        __syncthreads();

#pragma unroll
        for (int kk = 0; kk < 16; kk++) {
            float a_frag[8], b_frag[8];
            *(float4*)&a_frag[0] = *(float4*)&As[kk][ty*8];
            *(float4*)&a_frag[4] = *(float4*)&As[kk][ty*8 + 4];
            *(float4*)&b_frag[0] = *(float4*)&Bs[kk][tx*8];
            *(float4*)&b_frag[4] = *(float4*)&Bs[kk][tx*8 + 4];
#pragma unroll
            for (int i = 0; i < 8; i++)
#pragma unroll
                for (int j = 0; j < 8; j++)
                    acc[i][j] += a_frag[i] * b_frag[j];
        }
        __syncthreads();
    }

    // epilogue
#pragma unroll
    for (int i = 0; i < 8; i++) {
        const int m = row0 + ty*8 + i;
#pragma unroll
        for (int j = 0; j < 8; j++) {
            const int n = col0 + tx*8 + j;
            const float c = acc[i][j] + bias[n];
            if (out_mode == 0) {
                C[(size_t)m*GN + n] = c;
            } else {
                const int b  = m >> 8;       // /256
                const int nn = m & 255;
                const int h  = n >> 6;       // /64
                const int dk = n & 63;
                C[(((size_t)(b*PH + h))*PN + nn)*PDK + dk] = c;
            }
        }
    }
}

__global__ __launch_bounds__(256)
void qkv_gemm_kernel(const float* __restrict__ q_in, const float* __restrict__ k_in,
                     const float* __restrict__ v_in,
                     const float* __restrict__ Wq, const float* __restrict__ bq,
                     const float* __restrict__ Wk, const float* __restrict__ bk,
                     const float* __restrict__ Wv, const float* __restrict__ bv)
{
    const float* A; const float* W; const float* bias; float* C;
    if (blockIdx.z == 0)      { A = q_in; W = Wq; bias = bq; C = g_q; }
    else if (blockIdx.z == 1) { A = k_in; W = Wk; bias = bk; C = g_k; }
    else                      { A = v_in; W = Wv; bias = bv; C = g_v; }
    sgemm_body(A, W, bias, C, 1);
}

__global__ __launch_bounds__(256)
void out_gemm_kernel(const float* __restrict__ Wo, const float* __restrict__ bo,
                     float* __restrict__ out)
{
    sgemm_body(g_x, Wo, bo, out, 0);
}

// ---------------------------------------------------------------------------
// pd kernel: g_pd[b][i][j] = LAM_ADJ * adj[j]/(sum_j adj + eps)
//                          + LAM_DIST * softmax_j(-dist, masked)[j]
// one block per (b,i), 256 threads (one per j)
// ---------------------------------------------------------------------------
__global__ __launch_bounds__(256)
void pd_kernel(const float* __restrict__ adj, const float* __restrict__ dist,
               const int* __restrict__ mask)
{
    const int bi = blockIdx.x;        // b*256 + i
    const int b  = bi >> 8;
    const int j  = threadIdx.x;
    const int lane = j & 31, warp = j >> 5;

    const float a  = adj[(size_t)bi*PN + j];
    const int   mj = mask[(b << 8) + j];
    const float nd = mj ? -dist[(size_t)bi*PN + j] : -CUDART_INF_F;

    __shared__ float red[8];

    // --- sum of adj ---
    float v = a;
#pragma unroll
    for (int o = 16; o > 0; o >>= 1) v += __shfl_xor_sync(0xffffffffu, v, o);
    if (lane == 0) red[warp] = v;
    __syncthreads();
    float asum = red[0];
#pragma unroll
    for (int w = 1; w < 8; w++) asum += red[w];
    __syncthreads();

    // --- max of nd ---
    v = nd;
#pragma unroll
    for (int o = 16; o > 0; o >>= 1) v = fmaxf(v, __shfl_xor_sync(0xffffffffu, v, o));
    if (lane == 0) red[warp] = v;
    __syncthreads();
    float m = red[0];
#pragma unroll
    for (int w = 1; w < 8; w++) m = fmaxf(m, red[w]);
    __syncthreads();

    // --- sum of exp ---
    const float e = mj ? expf(nd - m) : 0.f;
    v = e;
#pragma unroll
    for (int o = 16; o > 0; o >>= 1) v += __shfl_xor_sync(0xffffffffu, v, o);
    if (lane == 0) red[warp] = v;
    __syncthreads();
    float esum = red[0];
#pragma unroll
    for (int w = 1; w < 8; w++) esum += red[w];

    g_pd[(size_t)bi*PN + j] = LAM_ADJ_C * a / (asum + 1e-6f) + LAM_DIST * (e / esum);
}

// ---------------------------------------------------------------------------
// fused attention: x[b,n,h*64+d] = sum_k (LAM_ATT*softmax(qk/8, mask) + pd) * v
// grid (8, H, B); block 256 = 8 warps; warp handles 4 q-rows.
// K,V staged in dynamic smem with stride 65 (conflict-free in both phases).
// ---------------------------------------------------------------------------
#define KV_STRIDE 65
#define ATT_SMEM_BYTES (2 * PN * KV_STRIDE * 4)

__global__ __launch_bounds__(256)
void attn_kernel(const int* __restrict__ mask)
{
    extern __shared__ float sm[];
    float* Ks = sm;                       // [256][65]
    float* Vs = sm + PN * KV_STRIDE;      // [256][65]
    __shared__ float qsh[8][4][64];
    __shared__ float pen_s[PN];           // 0 (valid) or -1e12 (masked key)

    const int h = blockIdx.y, b = blockIdx.z;
    const int tid = threadIdx.x;
    const int warp = tid >> 5, lane = tid & 31;

    const size_t head_off = ((size_t)(b*PH + h)) * PN * PDK;
    const float* Kg = g_k + head_off;
    const float* Vg = g_v + head_off;
    const float* Qg = g_q + head_off;

    // stage K, V
    for (int idx = tid * 4; idx < PN * PDK; idx += 256 * 4) {
        const int r = idx >> 6, d = idx & 63;
        float4 kv = *(const float4*)(Kg + idx);
        Ks[r*KV_STRIDE + d + 0] = kv.x;
        Ks[r*KV_STRIDE + d + 1] = kv.y;
        Ks[r*KV_STRIDE + d + 2] = kv.z;
        Ks[r*KV_STRIDE + d + 3] = kv.w;
        float4 vv = *(const float4*)(Vg + idx);
        Vs[r*KV_STRIDE + d + 0] = vv.x;
        Vs[r*KV_STRIDE + d + 1] = vv.y;
        Vs[r*KV_STRIDE + d + 2] = vv.z;
        Vs[r*KV_STRIDE + d + 3] = vv.w;
    }
    pen_s[tid] = mask[(b << 8) + tid] ? 0.f : -1e12f;

    // stage this warp's 4 q rows
    const int q0 = blockIdx.x * 32 + warp * 4;
#pragma unroll
    for (int r = 0; r < 4; r++) {
        qsh[warp][r][lane]      = Qg[(size_t)(q0 + r)*PDK + lane];
        qsh[warp][r][lane + 32] = Qg[(size_t)(q0 + r)*PDK + lane + 32];
    }
    __syncthreads();

    // scores: lane owns keys k = t*32 + lane, t=0..7; 4 q-rows per warp
    float s[8][4];
#pragma unroll
    for (int t = 0; t < 8; t++)
#pragma unroll
        for (int r = 0; r < 4; r++) s[t][r] = 0.f;

    for (int d = 0; d < 64; d++) {
        const float qd0 = qsh[warp][0][d];
        const float qd1 = qsh[warp][1][d];
        const float qd2 = qsh[warp][2][d];
        const float qd3 = qsh[warp][3][d];
#pragma unroll
        for (int t = 0; t < 8; t++) {
            const float kv = Ks[(t*32 + lane)*KV_STRIDE + d];
            s[t][0] += qd0 * kv;
            s[t][1] += qd1 * kv;
            s[t][2] += qd2 * kv;
            s[t][3] += qd3 * kv;
        }
    }

    float pen[8];
#pragma unroll
    for (int t = 0; t < 8; t++) pen[t] = pen_s[t*32 + lane];

    // softmax per row + combine with pd -> final weights in s[][]
    const float inv_sqrt = 0.125f;  // 1/sqrt(64)
#pragma unroll
    for (int r = 0; r < 4; r++) {
        float vv[8], m = -CUDART_INF_F;
#pragma unroll
        for (int t = 0; t < 8; t++) {
            vv[t] = s[t][r] * inv_sqrt + pen[t];
            m = fmaxf(m, vv[t]);
        }
#pragma unroll
        for (int o = 16; o > 0; o >>= 1) m = fmaxf(m, __shfl_xor_sync(0xffffffffu, m, o));
        float sum = 0.f;
#pragma unroll
        for (int t = 0; t < 8; t++) { vv[t] = expf(vv[t] - m); sum += vv[t]; }
#pragma unroll
        for (int o = 16; o > 0; o >>= 1) sum += __shfl_xor_sync(0xffffffffu, sum, o);
        const float scale = LAM_ATT / sum;
        const float* pdrow = g_pd + ((size_t)(b*PN) + (q0 + r)) * PN;
#pragma unroll
        for (int t = 0; t < 8; t++)
            s[t][r] = vv[t] * scale + __ldg(&pdrow[t*32 + lane]);
    }

    // AV: lane owns output dims {lane, lane+32}
    float acc[4][2];
#pragma unroll
    for (int r = 0; r < 4; r++) { acc[r][0] = 0.f; acc[r][1] = 0.f; }

#pragma unroll
    for (int t = 0; t < 8; t++) {
        for (int src = 0; src < 32; src++) {
            const int k = t*32 + src;
            const float v0 = Vs[k*KV_STRIDE + lane];
            const float v1 = Vs[k*KV_STRIDE + lane + 32];
#pragma unroll
            for (int r = 0; r < 4; r++) {
                const float wv = __shfl_sync(0xffffffffu, s[t][r], src);
                acc[r][0] += wv * v0;
                acc[r][1] += wv * v1;
            }
        }
    }

#pragma unroll
    for (int r = 0; r < 4; r++) {
        float* xr = g_x + ((size_t)(b*PN) + (q0 + r)) * PD + h * PDK;
        xr[lane]      = acc[r][0];
        xr[lane + 32] = acc[r][1];
    }
}

// ---------------------------------------------------------------------------
extern "C" void kernel_launch(void* const* d_in, const int* in_sizes, int n_in,
                              void* d_out, int out_size)
{
    const float* query = (const float*)d_in[0];
    const float* key   = (const float*)d_in[1];
    const float* value = (const float*)d_in[2];
    const float* adj   = (const float*)d_in[3];
    const float* dist  = (const float*)d_in[4];
    // d_in[5] edges_att unused
    const int*   mask  = (const int*)d_in[6];
    const float* Wq = (const float*)d_in[7];
    const float* bq = (const float*)d_in[8];
    const float* Wk = (const float*)d_in[9];
    const float* bk = (const float*)d_in[10];
    const float* Wv = (const float*)d_in[11];
    const float* bv = (const float*)d_in[12];
    const float* Wo = (const float*)d_in[13];
    const float* bo = (const float*)d_in[14];
    float* out = (float*)d_out;

    static bool attr_set = false;
    if (!attr_set) {
        cudaFuncSetAttribute(attn_kernel, cudaFuncAttributeMaxDynamicSharedMemorySize,
                             ATT_SMEM_BYTES);
        attr_set = true;
    }

    // 1) Q/K/V projections (head-split output layout)
    qkv_gemm_kernel<<<dim3(GN/128, GM/128, 3), 256>>>(
        query, key, value, Wq, bq, Wk, bk, Wv, bv);

    // 2) combined distance/adjacency map (head-independent)
    pd_kernel<<<PB*PN, 256>>>(adj, dist, mask);

    // 3) fused attention
    attn_kernel<<<dim3(PN/32, PH, PB), 256, ATT_SMEM_BYTES>>>(mask);

    // 4) output projection
    out_gemm_kernel<<<dim3(GN/128, GM/128, 1), 256>>>(Wo, bo, out);
}

// round 5
// speedup vs baseline: 2.1300x; 2.1300x over previous
#include <cuda_runtime.h>
#include <cuda_bf16.h>
#include <math_constants.h>
#include <cstdint>

// ---------------- problem constants ----------------
#define PB 16
#define PN 256
#define PD 1024
#define PH 16
#define PDK 64
#define GM (PB*PN)   // 4096

#define LAM_ATT 0.33f
#define LAM_DIST 0.33f
__device__ __constant__ float LAM_ADJ_C = (float)(1.0 - 0.33 - 0.33);

// ---------------- device scratch (no cudaMalloc allowed) ----------------
__device__ float g_q[PB*PH*PN*PDK];   // [b][h][n][dk]
__device__ float g_k[PB*PH*PN*PDK];
__device__ float g_v[PB*PH*PN*PDK];
__device__ float g_x[PB*PN*PD];       // attention output [b][n][d]
__device__ float g_pd[PB*PN*PN];      // LAM_DIST*p_dist + LAM_ADJ*p_adj

// split-bf16 operands
__device__ __nv_bfloat16 g_wt_hi[4][PD*PD];   // weights transposed: [n][k]
__device__ __nv_bfloat16 g_wt_lo[4][PD*PD];
__device__ __nv_bfloat16 g_ah[3][GM*PD];      // activations q/k/v: [m][k]
__device__ __nv_bfloat16 g_al[3][GM*PD];
__device__ __nv_bfloat16 g_xh[GM*PD];
__device__ __nv_bfloat16 g_xl[GM*PD];

// ---------------- helpers ----------------
__device__ __forceinline__ uint32_t smem_u32(const void* p) {
    uint32_t a;
    asm("{ .reg .u64 t; cvta.to.shared.u64 t, %1; cvt.u32.u64 %0, t; }" : "=r"(a) : "l"(p));
    return a;
}

__device__ __forceinline__ void cp16(uint32_t dst, const void* src) {
    asm volatile("cp.async.cg.shared.global [%0], [%1], 16;" :: "r"(dst), "l"(src) : "memory");
}
#define CP_COMMIT() asm volatile("cp.async.commit_group;" ::: "memory")
#define CP_WAIT0()  asm volatile("cp.async.wait_group 0;" ::: "memory")

__device__ __forceinline__ void ldm_x4(uint32_t a, uint32_t* r) {
    asm volatile("ldmatrix.sync.aligned.m8n8.x4.shared.b16 {%0,%1,%2,%3}, [%4];"
                 : "=r"(r[0]), "=r"(r[1]), "=r"(r[2]), "=r"(r[3]) : "r"(a));
}
__device__ __forceinline__ void ldm_x2(uint32_t a, uint32_t* r) {
    asm volatile("ldmatrix.sync.aligned.m8n8.x2.shared.b16 {%0,%1}, [%2];"
                 : "=r"(r[0]), "=r"(r[1]) : "r"(a));
}
__device__ __forceinline__ void mma16816(float* c, const uint32_t* a, const uint32_t* b) {
    asm volatile("mma.sync.aligned.m16n8k16.row.col.f32.bf16.bf16.f32 "
                 "{%0,%1,%2,%3}, {%4,%5,%6,%7}, {%8,%9}, {%0,%1,%2,%3};"
                 : "+f"(c[0]), "+f"(c[1]), "+f"(c[2]), "+f"(c[3])
                 : "r"(a[0]), "r"(a[1]), "r"(a[2]), "r"(a[3]), "r"(b[0]), "r"(b[1]));
}

// ---------------------------------------------------------------------------
// split/transpose prep kernels
// ---------------------------------------------------------------------------
__global__ __launch_bounds__(256)
void split_wt_kernel(const float* __restrict__ W0, const float* __restrict__ W1,
                     const float* __restrict__ W2, const float* __restrict__ W3)
{
    __shared__ float t[32][33];
    const int z = blockIdx.z;
    const float* W = (z == 0) ? W0 : (z == 1) ? W1 : (z == 2) ? W2 : W3;
    __nv_bfloat16* Hi = g_wt_hi[z];
    __nv_bfloat16* Lo = g_wt_lo[z];
    const int n0 = blockIdx.x * 32, k0 = blockIdx.y * 32;
    const int tx = threadIdx.x & 31, ty = threadIdx.x >> 5;
#pragma unroll
    for (int i = 0; i < 4; i++)
        t[ty + i*8][tx] = W[(size_t)(k0 + ty + i*8) * PD + n0 + tx];
    __syncthreads();
#pragma unroll
    for (int i = 0; i < 4; i++) {
        const int n = n0 + ty + i*8;
        const float v = t[tx][ty + i*8];
        const __nv_bfloat16 h = __float2bfloat16(v);
        Hi[(size_t)n * PD + k0 + tx] = h;
        Lo[(size_t)n * PD + k0 + tx] = __float2bfloat16(v - __bfloat162float(h));
    }
}

__device__ __forceinline__ void split_vec(const float* __restrict__ src,
                                          __nv_bfloat16* __restrict__ hi,
                                          __nv_bfloat16* __restrict__ lo, int i)
{
    const float4 v = ((const float4*)src)[i];
    const __nv_bfloat16 hx = __float2bfloat16(v.x);
    const __nv_bfloat16 hy = __float2bfloat16(v.y);
    const __nv_bfloat16 hz = __float2bfloat16(v.z);
    const __nv_bfloat16 hw = __float2bfloat16(v.w);
    __nv_bfloat162* H = (__nv_bfloat162*)hi;
    __nv_bfloat162* L = (__nv_bfloat162*)lo;
    H[i*2 + 0] = __halves2bfloat162(hx, hy);
    H[i*2 + 1] = __halves2bfloat162(hz, hw);
    L[i*2 + 0] = __halves2bfloat162(__float2bfloat16(v.x - __bfloat162float(hx)),
                                    __float2bfloat16(v.y - __bfloat162float(hy)));
    L[i*2 + 1] = __halves2bfloat162(__float2bfloat16(v.z - __bfloat162float(hz)),
                                    __float2bfloat16(v.w - __bfloat162float(hw)));
}

__global__ __launch_bounds__(256)
void split_qkv_kernel(const float* __restrict__ q, const float* __restrict__ k,
                      const float* __restrict__ v)
{
    const int z = blockIdx.y;
    const float* src = (z == 0) ? q : (z == 1) ? k : v;
    split_vec(src, g_ah[z], g_al[z], blockIdx.x * 256 + threadIdx.x);
}

__global__ __launch_bounds__(256)
void split_x_kernel()
{
    split_vec(g_x, g_xh, g_xl, blockIdx.x * 256 + threadIdx.x);
}

// ---------------------------------------------------------------------------
// mma.sync split-bf16 GEMM: C[4096x1024] = A @ W^T + bias
// CTA tile 128x128, warps 2x4 (warp tile 64x32), KC=32 double-buffered cp.async
// smem per chunk-buffer: Ah|Al|Bh|Bl each 128x32 bf16 = 8KB -> 32KB; x2 = 64KB
// swizzle: 16B segment s' = s ^ ((row>>1)&3)   (row stride 64B)
// ---------------------------------------------------------------------------
#define KCH 32
#define VOFF 8192           // bytes per version plane
#define BUFOFF 32768
#define GEMM_DYN 65536

__device__ __forceinline__ void stage_chunk(
    uint32_t sb, const __nv_bfloat16* __restrict__ Ah, const __nv_bfloat16* __restrict__ Al,
    const __nv_bfloat16* __restrict__ Bh, const __nv_bfloat16* __restrict__ Bl,
    int m0, int n0, int kt, int tid)
{
#pragma unroll
    for (int i = 0; i < 2; ++i) {
        const int idx = tid + i * 256;          // 0..511
        const int row = idx >> 2;               // 0..127
        const int seg = idx & 3;
        const uint32_t doff = (uint32_t)(row * 64 + ((seg ^ ((row >> 1) & 3)) * 16));
        const size_t aoff = (size_t)(m0 + row) * PD + kt + seg * 8;
        const size_t boff = (size_t)(n0 + row) * PD + kt + seg * 8;
        cp16(sb + 0*VOFF + doff, Ah + aoff);
        cp16(sb + 1*VOFF + doff, Al + aoff);
        cp16(sb + 2*VOFF + doff, Bh + boff);
        cp16(sb + 3*VOFF + doff, Bl + boff);
    }
}

__device__ __forceinline__ void gemm_core(
    const __nv_bfloat16* __restrict__ Ah, const __nv_bfloat16* __restrict__ Al,
    const __nv_bfloat16* __restrict__ Bh, const __nv_bfloat16* __restrict__ Bl,
    const float* __restrict__ bias, float* __restrict__ C, int out_mode)
{
    extern __shared__ char dsm[];
    const uint32_t sb = smem_u32(dsm);
    const int tid  = threadIdx.x;
    const int wid  = tid >> 5;
    const int lane = tid & 31;
    const int m0 = blockIdx.y * 128;
    const int n0 = blockIdx.x * 128;

    const int wm = (wid & 1) * 64;     // warp row offset (2 rows of warps)
    const int wn = (wid >> 1) * 32;    // warp col offset (4 cols of warps)

    // ldmatrix per-lane base offsets (kstep 0)
    const int ag   = lane >> 3;                      // 0..3
    const int arow = wm + (lane & 7) + 8 * (ag & 1);
    const int aseg = ag >> 1;
    const uint32_t a_off = (uint32_t)(arow * 64 + ((aseg ^ ((arow >> 1) & 3)) * 16));

    const int bg   = (lane >> 3) & 1;
    const int brow = wn + (lane & 7);
    const uint32_t b_off = (uint32_t)(brow * 64 + ((bg ^ ((brow >> 1) & 3)) * 16));

    float acc[4][4][4];
#pragma unroll
    for (int mt = 0; mt < 4; mt++)
#pragma unroll
        for (int nt = 0; nt < 4; nt++)
#pragma unroll
            for (int r = 0; r < 4; r++) acc[mt][nt][r] = 0.f;

    stage_chunk(sb, Ah, Al, Bh, Bl, m0, n0, 0, tid);
    CP_COMMIT();

    for (int c = 0; c < PD / KCH; ++c) {
        CP_WAIT0();
        __syncthreads();
        if (c + 1 < PD / KCH) {
            stage_chunk(sb + ((c + 1) & 1) * BUFOFF, Ah, Al, Bh, Bl,
                        m0, n0, (c + 1) * KCH, tid);
            CP_COMMIT();
        }
        const uint32_t buf = sb + (c & 1) * BUFOFF;

#pragma unroll
        for (int ks = 0; ks < 2; ++ks) {
            const uint32_t kx = ks * 32;     // seg field xor for second k16
            uint32_t ah[4][4], al[4][4], bh[4][2], bl[4][2];
#pragma unroll
            for (int mt = 0; mt < 4; mt++)
                ldm_x4(buf + 0*VOFF + mt*1024 + (a_off ^ kx), ah[mt]);
#pragma unroll
            for (int nt = 0; nt < 4; nt++)
                ldm_x2(buf + 2*VOFF + nt*512 + (b_off ^ kx), bh[nt]);
#pragma unroll
            for (int mt = 0; mt < 4; mt++)
#pragma unroll
                for (int nt = 0; nt < 4; nt++)
                    mma16816(acc[mt][nt], ah[mt], bh[nt]);

#pragma unroll
            for (int mt = 0; mt < 4; mt++)
                ldm_x4(buf + 1*VOFF + mt*1024 + (a_off ^ kx), al[mt]);
#pragma unroll
            for (int mt = 0; mt < 4; mt++)
#pragma unroll
                for (int nt = 0; nt < 4; nt++)
                    mma16816(acc[mt][nt], al[mt], bh[nt]);

#pragma unroll
            for (int nt = 0; nt < 4; nt++)
                ldm_x2(buf + 3*VOFF + nt*512 + (b_off ^ kx), bl[nt]);
#pragma unroll
            for (int mt = 0; mt < 4; mt++)
#pragma unroll
                for (int nt = 0; nt < 4; nt++)
                    mma16816(acc[mt][nt], ah[mt], bl[nt]);
        }
        __syncthreads();
    }

    // epilogue: direct register -> gmem (float2 stores), with bias
    const int g4  = lane >> 2;
    const int t4  = lane & 3;
#pragma unroll
    for (int nt = 0; nt < 4; nt++) {
        const int col = n0 + wn + nt * 8 + t4 * 2;
        const float2 bv = *(const float2*)(bias + col);
#pragma unroll
        for (int mt = 0; mt < 4; mt++) {
            const int row = m0 + wm + mt * 16 + g4;
            float2 v0, v1;
            v0.x = acc[mt][nt][0] + bv.x;  v0.y = acc[mt][nt][1] + bv.y;
            v1.x = acc[mt][nt][2] + bv.x;  v1.y = acc[mt][nt][3] + bv.y;
            if (out_mode == 0) {
                *(float2*)(C + (size_t)row * PD + col)       = v0;
                *(float2*)(C + (size_t)(row + 8) * PD + col) = v1;
            } else {
                const int b = row >> 8, h = col >> 6, dk = col & 63;
                const int nn0 = row & 255;
                float* base = C + (((size_t)(b * PH + h)) * PN) * PDK + dk;
                *(float2*)(base + (size_t)nn0 * PDK)       = v0;
                *(float2*)(base + (size_t)(nn0 + 8) * PDK) = v1;
            }
        }
    }
}

__global__ __launch_bounds__(256, 1)
void qkv_mma_kernel(const float* __restrict__ bq, const float* __restrict__ bk,
                    const float* __restrict__ bv)
{
    const int z = blockIdx.z;
    gemm_core(g_ah[z], g_al[z], g_wt_hi[z], g_wt_lo[z],
              (z == 0) ? bq : (z == 1) ? bk : bv,
              (z == 0) ? g_q : (z == 1) ? g_k : g_v, 1);
}

__global__ __launch_bounds__(256, 1)
void out_mma_kernel(const float* __restrict__ bo, float* __restrict__ out)
{
    gemm_core(g_xh, g_xl, g_wt_hi[3], g_wt_lo[3], bo, out, 0);
}

// ---------------------------------------------------------------------------
// pd kernel
// ---------------------------------------------------------------------------
__global__ __launch_bounds__(256)
void pd_kernel(const float* __restrict__ adj, const float* __restrict__ dist,
               const int* __restrict__ mask)
{
    const int bi = blockIdx.x;
    const int b  = bi >> 8;
    const int j  = threadIdx.x;
    const int lane = j & 31, warp = j >> 5;

    const float a  = adj[(size_t)bi*PN + j];
    const int   mj = mask[(b << 8) + j];
    const float nd = mj ? -dist[(size_t)bi*PN + j] : -CUDART_INF_F;

    __shared__ float red[8];

    float v = a;
#pragma unroll
    for (int o = 16; o > 0; o >>= 1) v += __shfl_xor_sync(0xffffffffu, v, o);
    if (lane == 0) red[warp] = v;
    __syncthreads();
    float asum = red[0];
#pragma unroll
    for (int w = 1; w < 8; w++) asum += red[w];
    __syncthreads();

    v = nd;
#pragma unroll
    for (int o = 16; o > 0; o >>= 1) v = fmaxf(v, __shfl_xor_sync(0xffffffffu, v, o));
    if (lane == 0) red[warp] = v;
    __syncthreads();
    float m = red[0];
#pragma unroll
    for (int w = 1; w < 8; w++) m = fmaxf(m, red[w]);
    __syncthreads();

    const float e = mj ? expf(nd - m) : 0.f;
    v = e;
#pragma unroll
    for (int o = 16; o > 0; o >>= 1) v += __shfl_xor_sync(0xffffffffu, v, o);
    if (lane == 0) red[warp] = v;
    __syncthreads();
    float esum = red[0];
#pragma unroll
    for (int w = 1; w < 8; w++) esum += red[w];

    g_pd[(size_t)bi*PN + j] = LAM_ADJ_C * a / (asum + 1e-6f) + LAM_DIST * (e / esum);
}

// ---------------------------------------------------------------------------
// fused attention (shfl-free AV via smem-staged weights)
// ---------------------------------------------------------------------------
#define KV_STRIDE 65
#define WS_STRIDE 260
#define ATT_DYN ((2*PN*KV_STRIDE + 32*WS_STRIDE) * 4)

__global__ __launch_bounds__(256)
void attn_kernel(const int* __restrict__ mask)
{
    extern __shared__ float sm[];
    float* Ks = sm;
    float* Vs = sm + PN * KV_STRIDE;
    float* Ws = sm + 2 * PN * KV_STRIDE;   // [32][260]
    __shared__ float qsh[8][4][64];
    __shared__ float pen_s[PN];

    const int h = blockIdx.y, b = blockIdx.z;
    const int tid = threadIdx.x;
    const int warp = tid >> 5, lane = tid & 31;

    const size_t head_off = ((size_t)(b*PH + h)) * PN * PDK;
    const float* Kg = g_k + head_off;
    const float* Vg = g_v + head_off;
    const float* Qg = g_q + head_off;

    for (int idx = tid * 4; idx < PN * PDK; idx += 256 * 4) {
        const int r = idx >> 6, d = idx & 63;
        float4 kv = *(const float4*)(Kg + idx);
        Ks[r*KV_STRIDE + d + 0] = kv.x;
        Ks[r*KV_STRIDE + d + 1] = kv.y;
        Ks[r*KV_STRIDE + d + 2] = kv.z;
        Ks[r*KV_STRIDE + d + 3] = kv.w;
        float4 vv = *(const float4*)(Vg + idx);
        Vs[r*KV_STRIDE + d + 0] = vv.x;
        Vs[r*KV_STRIDE + d + 1] = vv.y;
        Vs[r*KV_STRIDE + d + 2] = vv.z;
        Vs[r*KV_STRIDE + d + 3] = vv.w;
    }
    pen_s[tid] = mask[(b << 8) + tid] ? 0.f : -1e12f;

    const int q0 = blockIdx.x * 32 + warp * 4;
#pragma unroll
    for (int r = 0; r < 4; r++) {
        qsh[warp][r][lane]      = Qg[(size_t)(q0 + r)*PDK + lane];
        qsh[warp][r][lane + 32] = Qg[(size_t)(q0 + r)*PDK + lane + 32];
    }
    __syncthreads();

    // QK^T: lane owns keys k = t*32+lane
    float s[8][4];
#pragma unroll
    for (int t = 0; t < 8; t++)
#pragma unroll
        for (int r = 0; r < 4; r++) s[t][r] = 0.f;

    for (int d = 0; d < 64; d++) {
        const float qd0 = qsh[warp][0][d];
        const float qd1 = qsh[warp][1][d];
        const float qd2 = qsh[warp][2][d];
        const float qd3 = qsh[warp][3][d];
#pragma unroll
        for (int t = 0; t < 8; t++) {
            const float kv = Ks[(t*32 + lane)*KV_STRIDE + d];
            s[t][0] += qd0 * kv;
            s[t][1] += qd1 * kv;
            s[t][2] += qd2 * kv;
            s[t][3] += qd3 * kv;
        }
    }

    float pen[8];
#pragma unroll
    for (int t = 0; t < 8; t++) pen[t] = pen_s[t*32 + lane];

    const float inv_sqrt = 0.125f;
#pragma unroll
    for (int r = 0; r < 4; r++) {
        float vv[8], m = -CUDART_INF_F;
#pragma unroll
        for (int t = 0; t < 8; t++) {
            vv[t] = s[t][r] * inv_sqrt + pen[t];
            m = fmaxf(m, vv[t]);
        }
#pragma unroll
        for (int o = 16; o > 0; o >>= 1) m = fmaxf(m, __shfl_xor_sync(0xffffffffu, m, o));
        float sum = 0.f;
#pragma unroll
        for (int t = 0; t < 8; t++) { vv[t] = expf(vv[t] - m); sum += vv[t]; }
#pragma unroll
        for (int o = 16; o > 0; o >>= 1) sum += __shfl_xor_sync(0xffffffffu, sum, o);
        const float scale = LAM_ATT / sum;
        const float* pdrow = g_pd + ((size_t)(b*PN) + (q0 + r)) * PN;
#pragma unroll
        for (int t = 0; t < 8; t++)
            s[t][r] = vv[t] * scale + __ldg(&pdrow[t*32 + lane]);
    }

    // stage weights to smem (warp-local rows), then FFMA-based AV (no shfl)
    const int rowb = warp * 4;
#pragma unroll
    for (int r = 0; r < 4; ++r)
#pragma unroll
        for (int t = 0; t < 8; ++t)
            Ws[(rowb + r)*WS_STRIDE + t*32 + lane] = s[t][r];
    __syncwarp();

    float acc[4][2];
#pragma unroll
    for (int r = 0; r < 4; r++) { acc[r][0] = 0.f; acc[r][1] = 0.f; }

    const float* w0p = Ws + (rowb + 0)*WS_STRIDE;
    const float* w1p = Ws + (rowb + 1)*WS_STRIDE;
    const float* w2p = Ws + (rowb + 2)*WS_STRIDE;
    const float* w3p = Ws + (rowb + 3)*WS_STRIDE;

    for (int k4 = 0; k4 < 64; ++k4) {
        float wv[4][4];
        *(float4*)&wv[0][0] = *(const float4*)(w0p + k4*4);
        *(float4*)&wv[1][0] = *(const float4*)(w1p + k4*4);
        *(float4*)&wv[2][0] = *(const float4*)(w2p + k4*4);
        *(float4*)&wv[3][0] = *(const float4*)(w3p + k4*4);
#pragma unroll
        for (int kk = 0; kk < 4; ++kk) {
            const int k = k4*4 + kk;
            const float v0 = Vs[k*KV_STRIDE + lane];
            const float v1 = Vs[k*KV_STRIDE + lane + 32];
            acc[0][0] += wv[0][kk] * v0;  acc[0][1] += wv[0][kk] * v1;
            acc[1][0] += wv[1][kk] * v0;  acc[1][1] += wv[1][kk] * v1;
            acc[2][0] += wv[2][kk] * v0;  acc[2][1] += wv[2][kk] * v1;
            acc[3][0] += wv[3][kk] * v0;  acc[3][1] += wv[3][kk] * v1;
        }
    }

#pragma unroll
    for (int r = 0; r < 4; r++) {
        float* xr = g_x + ((size_t)(b*PN) + (q0 + r)) * PD + h * PDK;
        xr[lane]      = acc[r][0];
        xr[lane + 32] = acc[r][1];
    }
}

// ---------------------------------------------------------------------------
extern "C" void kernel_launch(void* const* d_in, const int* in_sizes, int n_in,
                              void* d_out, int out_size)
{
    const float* query = (const float*)d_in[0];
    const float* key   = (const float*)d_in[1];
    const float* value = (const float*)d_in[2];
    const float* adj   = (const float*)d_in[3];
    const float* dist  = (const float*)d_in[4];
    const int*   mask  = (const int*)d_in[6];
    const float* bq = (const float*)d_in[8];
    const float* bk = (const float*)d_in[10];
    const float* bv = (const float*)d_in[12];
    const float* Wq = (const float*)d_in[7];
    const float* Wk = (const float*)d_in[9];
    const float* Wv = (const float*)d_in[11];
    const float* Wo = (const float*)d_in[13];
    const float* bo = (const float*)d_in[14];
    float* out = (float*)d_out;

    static bool attr_set = false;
    if (!attr_set) {
        cudaFuncSetAttribute(qkv_mma_kernel, cudaFuncAttributeMaxDynamicSharedMemorySize, GEMM_DYN);
        cudaFuncSetAttribute(out_mma_kernel, cudaFuncAttributeMaxDynamicSharedMemorySize, GEMM_DYN);
        cudaFuncSetAttribute(attn_kernel, cudaFuncAttributeMaxDynamicSharedMemorySize, ATT_DYN);
        attr_set = true;
    }

    // prep: weight transpose+split, activation split
    split_wt_kernel<<<dim3(32, 32, 4), 256>>>(Wq, Wk, Wv, Wo);
    split_qkv_kernel<<<dim3(GM*PD/4/256, 3), 256>>>(query, key, value);

    // QKV projections on tensor cores via mma.sync (head-split output)
    qkv_mma_kernel<<<dim3(PD/128, GM/128, 3), 256, GEMM_DYN>>>(bq, bk, bv);

    // combined distance/adjacency map
    pd_kernel<<<PB*PN, 256>>>(adj, dist, mask);

    // fused attention
    attn_kernel<<<dim3(PN/32, PH, PB), 256, ATT_DYN>>>(mask);

    // output projection
    split_x_kernel<<<GM*PD/4/256, 256>>>();
    out_mma_kernel<<<dim3(PD/128, GM/128, 1), 256, GEMM_DYN>>>(bo, out);
}

// round 8
// speedup vs baseline: 2.8342x; 1.3306x over previous
#include <cuda_runtime.h>
#include <cuda_bf16.h>
#include <math_constants.h>
#include <cstdint>

// ---------------- problem constants ----------------
#define PB 16
#define PN 256
#define PD 1024
#define PH 16
#define PDK 64
#define GM (PB*PN)   // 4096

#define LAM_ATT 0.33f
#define LAM_DIST 0.33f
__device__ __constant__ float LAM_ADJ_C = (float)(1.0 - 0.33 - 0.33);

// ---------------- device scratch (no cudaMalloc allowed) ----------------
__device__ float g_pd[PB*PN*PN];      // LAM_DIST*p_dist + LAM_ADJ*p_adj

// split-bf16 operands
__device__ __nv_bfloat16 g_wt_hi[4][PD*PD];   // weights transposed: [n][k]
__device__ __nv_bfloat16 g_wt_lo[4][PD*PD];
__device__ __nv_bfloat16 g_ah[3][GM*PD];      // activations q/k/v: [m][k]
__device__ __nv_bfloat16 g_al[3][GM*PD];
// projected Q/K/V, split bf16, head layout [b][h][n][dk]
__device__ __nv_bfloat16 g_qh[GM*PD]; __device__ __nv_bfloat16 g_ql[GM*PD];
__device__ __nv_bfloat16 g_kh[GM*PD]; __device__ __nv_bfloat16 g_kl[GM*PD];
__device__ __nv_bfloat16 g_vh[GM*PD]; __device__ __nv_bfloat16 g_vl[GM*PD];
// attention output, split bf16, [m][d]
__device__ __nv_bfloat16 g_xh[GM*PD]; __device__ __nv_bfloat16 g_xl[GM*PD];

// ---------------- helpers ----------------
__device__ __forceinline__ uint32_t bf2_u32(__nv_bfloat162 v) {
    union { __nv_bfloat162 b; uint32_t u; } c;
    c.b = v;
    return c.u;
}
__device__ __forceinline__ uint32_t smem_u32(const void* p) {
    uint32_t a;
    asm("{ .reg .u64 t; cvta.to.shared.u64 t, %1; cvt.u32.u64 %0, t; }" : "=r"(a) : "l"(p));
    return a;
}
__device__ __forceinline__ void cp16(uint32_t dst, const void* src) {
    asm volatile("cp.async.cg.shared.global [%0], [%1], 16;" :: "r"(dst), "l"(src) : "memory");
}
#define CP_COMMIT() asm volatile("cp.async.commit_group;" ::: "memory")
#define CP_WAIT0()  asm volatile("cp.async.wait_group 0;" ::: "memory")

__device__ __forceinline__ void ldm_x4(uint32_t a, uint32_t* r) {
    asm volatile("ldmatrix.sync.aligned.m8n8.x4.shared.b16 {%0,%1,%2,%3}, [%4];"
                 : "=r"(r[0]), "=r"(r[1]), "=r"(r[2]), "=r"(r[3]) : "r"(a));
}
__device__ __forceinline__ void ldm_x2(uint32_t a, uint32_t* r) {
    asm volatile("ldmatrix.sync.aligned.m8n8.x2.shared.b16 {%0,%1}, [%2];"
                 : "=r"(r[0]), "=r"(r[1]) : "r"(a));
}
__device__ __forceinline__ void ldm_x2_t(uint32_t a, uint32_t* r) {
    asm volatile("ldmatrix.sync.aligned.m8n8.x2.trans.shared.b16 {%0,%1}, [%2];"
                 : "=r"(r[0]), "=r"(r[1]) : "r"(a));
}
__device__ __forceinline__ void mma16816(float* c, const uint32_t* a, const uint32_t* b) {
    asm volatile("mma.sync.aligned.m16n8k16.row.col.f32.bf16.bf16.f32 "
                 "{%0,%1,%2,%3}, {%4,%5,%6,%7}, {%8,%9}, {%0,%1,%2,%3};"
                 : "+f"(c[0]), "+f"(c[1]), "+f"(c[2]), "+f"(c[3])
                 : "r"(a[0]), "r"(a[1]), "r"(a[2]), "r"(a[3]), "r"(b[0]), "r"(b[1]));
}
__device__ __forceinline__ void sts32f(uint32_t addr, float v) {
    asm volatile("st.shared.f32 [%0], %1;" :: "r"(addr), "f"(v) : "memory");
}
__device__ __forceinline__ float lds32f(uint32_t addr) {
    float v; asm volatile("ld.shared.f32 %0, [%1];" : "=f"(v) : "r"(addr)); return v;
}
__device__ __forceinline__ float4 lds128f(uint32_t addr) {
    float4 v;
    asm volatile("ld.shared.v4.f32 {%0,%1,%2,%3}, [%4];"
                 : "=f"(v.x), "=f"(v.y), "=f"(v.z), "=f"(v.w) : "r"(addr));
    return v;
}
__device__ __forceinline__ void sts128u(uint32_t addr, uint32_t a, uint32_t b, uint32_t c, uint32_t d) {
    asm volatile("st.shared.v4.b32 [%0], {%1,%2,%3,%4};"
                 :: "r"(addr), "r"(a), "r"(b), "r"(c), "r"(d) : "memory");
}
__device__ __forceinline__ void sts64f(uint32_t addr, float a, float b) {
    asm volatile("st.shared.v2.f32 [%0], {%1,%2};" :: "r"(addr), "f"(a), "f"(b) : "memory");
}

// ---------------------------------------------------------------------------
// split/transpose prep kernels
// ---------------------------------------------------------------------------
__global__ __launch_bounds__(256)
void split_wt_kernel(const float* __restrict__ W0, const float* __restrict__ W1,
                     const float* __restrict__ W2, const float* __restrict__ W3)
{
    __shared__ float t[32][33];
    const int z = blockIdx.z;
    const float* W = (z == 0) ? W0 : (z == 1) ? W1 : (z == 2) ? W2 : W3;
    __nv_bfloat16* Hi = g_wt_hi[z];
    __nv_bfloat16* Lo = g_wt_lo[z];
    const int n0 = blockIdx.x * 32, k0 = blockIdx.y * 32;
    const int tx = threadIdx.x & 31, ty = threadIdx.x >> 5;
#pragma unroll
    for (int i = 0; i < 4; i++)
        t[ty + i*8][tx] = W[(size_t)(k0 + ty + i*8) * PD + n0 + tx];
    __syncthreads();
#pragma unroll
    for (int i = 0; i < 4; i++) {
        const int n = n0 + ty + i*8;
        const float v = t[tx][ty + i*8];
        const __nv_bfloat16 h = __float2bfloat16(v);
        Hi[(size_t)n * PD + k0 + tx] = h;
        Lo[(size_t)n * PD + k0 + tx] = __float2bfloat16(v - __bfloat162float(h));
    }
}

__device__ __forceinline__ void split_vec(const float* __restrict__ src,
                                          __nv_bfloat16* __restrict__ hi,
                                          __nv_bfloat16* __restrict__ lo, int i)
{
    const float4 v = ((const float4*)src)[i];
    const __nv_bfloat16 hx = __float2bfloat16(v.x);
    const __nv_bfloat16 hy = __float2bfloat16(v.y);
    const __nv_bfloat16 hz = __float2bfloat16(v.z);
    const __nv_bfloat16 hw = __float2bfloat16(v.w);
    __nv_bfloat162* H = (__nv_bfloat162*)hi;
    __nv_bfloat162* L = (__nv_bfloat162*)lo;
    H[i*2 + 0] = __halves2bfloat162(hx, hy);
    H[i*2 + 1] = __halves2bfloat162(hz, hw);
    L[i*2 + 0] = __halves2bfloat162(__float2bfloat16(v.x - __bfloat162float(hx)),
                                    __float2bfloat16(v.y - __bfloat162float(hy)));
    L[i*2 + 1] = __halves2bfloat162(__float2bfloat16(v.z - __bfloat162float(hz)),
                                    __float2bfloat16(v.w - __bfloat162float(hw)));
}

__global__ __launch_bounds__(256)
void split_qkv_kernel(const float* __restrict__ q, const float* __restrict__ k,
                      const float* __restrict__ v)
{
    const int z = blockIdx.y;
    const float* src = (z == 0) ? q : (z == 1) ? k : v;
    split_vec(src, g_ah[z], g_al[z], blockIdx.x * 256 + threadIdx.x);
}

// ---------------------------------------------------------------------------
// mma.sync split-bf16 GEMM (CTA 128x128, KC=32, double-buffered cp.async)
// out_mode 0: fp32 row-major [m][n]
// out_mode 1: split bf16 head layout [b][h][n][dk] into (Ch, Cl)
// ---------------------------------------------------------------------------
#define KCH 32
#define VOFF 8192
#define BUFOFF 32768
#define GEMM_DYN 65536

__device__ __forceinline__ void stage_chunk(
    uint32_t sb, const __nv_bfloat16* __restrict__ Ah, const __nv_bfloat16* __restrict__ Al,
    const __nv_bfloat16* __restrict__ Bh, const __nv_bfloat16* __restrict__ Bl,
    int m0, int n0, int kt, int tid)
{
#pragma unroll
    for (int i = 0; i < 2; ++i) {
        const int idx = tid + i * 256;
        const int row = idx >> 2;
        const int seg = idx & 3;
        const uint32_t doff = (uint32_t)(row * 64 + ((seg ^ ((row >> 1) & 3)) * 16));
        const size_t aoff = (size_t)(m0 + row) * PD + kt + seg * 8;
        const size_t boff = (size_t)(n0 + row) * PD + kt + seg * 8;
        cp16(sb + 0*VOFF + doff, Ah + aoff);
        cp16(sb + 1*VOFF + doff, Al + aoff);
        cp16(sb + 2*VOFF + doff, Bh + boff);
        cp16(sb + 3*VOFF + doff, Bl + boff);
    }
}

__device__ __forceinline__ void gemm_core(
    const __nv_bfloat16* __restrict__ Ah, const __nv_bfloat16* __restrict__ Al,
    const __nv_bfloat16* __restrict__ Bh, const __nv_bfloat16* __restrict__ Bl,
    const float* __restrict__ bias, float* __restrict__ C,
    __nv_bfloat16* __restrict__ Ch, __nv_bfloat16* __restrict__ Cl, int out_mode)
{
    extern __shared__ char dsm[];
    const uint32_t sb = smem_u32(dsm);
    const int tid  = threadIdx.x;
    const int wid  = tid >> 5;
    const int lane = tid & 31;
    const int m0 = blockIdx.y * 128;
    const int n0 = blockIdx.x * 128;

    const int wm = (wid & 1) * 64;
    const int wn = (wid >> 1) * 32;

    const int ag   = lane >> 3;
    const int arow = wm + (lane & 7) + 8 * (ag & 1);
    const int aseg = ag >> 1;
    const uint32_t a_off = (uint32_t)(arow * 64 + ((aseg ^ ((arow >> 1) & 3)) * 16));

    const int bg   = (lane >> 3) & 1;
    const int brow = wn + (lane & 7);
    const uint32_t b_off = (uint32_t)(brow * 64 + ((bg ^ ((brow >> 1) & 3)) * 16));

    float acc[4][4][4];
#pragma unroll
    for (int mt = 0; mt < 4; mt++)
#pragma unroll
        for (int nt = 0; nt < 4; nt++)
#pragma unroll
            for (int r = 0; r < 4; r++) acc[mt][nt][r] = 0.f;

    stage_chunk(sb, Ah, Al, Bh, Bl, m0, n0, 0, tid);
    CP_COMMIT();

    for (int c = 0; c < PD / KCH; ++c) {
        CP_WAIT0();
        __syncthreads();
        if (c + 1 < PD / KCH) {
            stage_chunk(sb + ((c + 1) & 1) * BUFOFF, Ah, Al, Bh, Bl,
                        m0, n0, (c + 1) * KCH, tid);
            CP_COMMIT();
        }
        const uint32_t buf = sb + (c & 1) * BUFOFF;

#pragma unroll
        for (int ks = 0; ks < 2; ++ks) {
            const uint32_t kx = ks * 32;
            uint32_t ah[4][4], al[4][4], bh[4][2], bl[4][2];
#pragma unroll
            for (int mt = 0; mt < 4; mt++)
                ldm_x4(buf + 0*VOFF + mt*1024 + (a_off ^ kx), ah[mt]);
#pragma unroll
            for (int nt = 0; nt < 4; nt++)
                ldm_x2(buf + 2*VOFF + nt*512 + (b_off ^ kx), bh[nt]);
#pragma unroll
            for (int mt = 0; mt < 4; mt++)
#pragma unroll
                for (int nt = 0; nt < 4; nt++)
                    mma16816(acc[mt][nt], ah[mt], bh[nt]);
#pragma unroll
            for (int mt = 0; mt < 4; mt++)
                ldm_x4(buf + 1*VOFF + mt*1024 + (a_off ^ kx), al[mt]);
#pragma unroll
            for (int mt = 0; mt < 4; mt++)
#pragma unroll
                for (int nt = 0; nt < 4; nt++)
                    mma16816(acc[mt][nt], al[mt], bh[nt]);
#pragma unroll
            for (int nt = 0; nt < 4; nt++)
                ldm_x2(buf + 3*VOFF + nt*512 + (b_off ^ kx), bl[nt]);
#pragma unroll
            for (int mt = 0; mt < 4; mt++)
#pragma unroll
                for (int nt = 0; nt < 4; nt++)
                    mma16816(acc[mt][nt], ah[mt], bl[nt]);
        }
        __syncthreads();
    }

    const int g4 = lane >> 2;
    const int t4 = lane & 3;
#pragma unroll
    for (int nt = 0; nt < 4; nt++) {
        const int col = n0 + wn + nt * 8 + t4 * 2;
        const float2 bv = *(const float2*)(bias + col);
#pragma unroll
        for (int mt = 0; mt < 4; mt++) {
            const int row = m0 + wm + mt * 16 + g4;
            float2 v0, v1;
            v0.x = acc[mt][nt][0] + bv.x;  v0.y = acc[mt][nt][1] + bv.y;
            v1.x = acc[mt][nt][2] + bv.x;  v1.y = acc[mt][nt][3] + bv.y;
            if (out_mode == 0) {
                *(float2*)(C + (size_t)row * PD + col)       = v0;
                *(float2*)(C + (size_t)(row + 8) * PD + col) = v1;
            } else {
                const int b = row >> 8, h = col >> 6, dk = col & 63;
                const int nn = row & 255;
                const size_t base = (((size_t)(b * PH + h)) * PN + nn) * PDK + dk;
                const __nv_bfloat16 h0x = __float2bfloat16(v0.x);
                const __nv_bfloat16 h0y = __float2bfloat16(v0.y);
                const __nv_bfloat16 h1x = __float2bfloat16(v1.x);
                const __nv_bfloat16 h1y = __float2bfloat16(v1.y);
                *(__nv_bfloat162*)(Ch + base) = __halves2bfloat162(h0x, h0y);
                *(__nv_bfloat162*)(Cl + base) =
                    __halves2bfloat162(__float2bfloat16(v0.x - __bfloat162float(h0x)),
                                       __float2bfloat16(v0.y - __bfloat162float(h0y)));
                *(__nv_bfloat162*)(Ch + base + 8*PDK) = __halves2bfloat162(h1x, h1y);
                *(__nv_bfloat162*)(Cl + base + 8*PDK) =
                    __halves2bfloat162(__float2bfloat16(v1.x - __bfloat162float(h1x)),
                                       __float2bfloat16(v1.y - __bfloat162float(h1y)));
            }
        }
    }
}

__global__ __launch_bounds__(256, 1)
void qkv_mma_kernel(const float* __restrict__ bq, const float* __restrict__ bk,
                    const float* __restrict__ bv)
{
    const int z = blockIdx.z;
    __nv_bfloat16* Ch = (z == 0) ? g_qh : (z == 1) ? g_kh : g_vh;
    __nv_bfloat16* Cl = (z == 0) ? g_ql : (z == 1) ? g_kl : g_vl;
    gemm_core(g_ah[z], g_al[z], g_wt_hi[z], g_wt_lo[z],
              (z == 0) ? bq : (z == 1) ? bk : bv, nullptr, Ch, Cl, 1);
}

__global__ __launch_bounds__(256, 1)
void out_mma_kernel(const float* __restrict__ bo, float* __restrict__ out)
{
    gemm_core(g_xh, g_xl, g_wt_hi[3], g_wt_lo[3], bo, out, nullptr, nullptr, 0);
}

// ---------------------------------------------------------------------------
// pd kernel
// ---------------------------------------------------------------------------
__global__ __launch_bounds__(256)
void pd_kernel(const float* __restrict__ adj, const float* __restrict__ dist,
               const int* __restrict__ mask)
{
    const int bi = blockIdx.x;
    const int b  = bi >> 8;
    const int j  = threadIdx.x;
    const int lane = j & 31, warp = j >> 5;

    const float a  = adj[(size_t)bi*PN + j];
    const int   mj = mask[(b << 8) + j];
    const float nd = mj ? -dist[(size_t)bi*PN + j] : -CUDART_INF_F;

    __shared__ float red[8];

    float v = a;
#pragma unroll
    for (int o = 16; o > 0; o >>= 1) v += __shfl_xor_sync(0xffffffffu, v, o);
    if (lane == 0) red[warp] = v;
    __syncthreads();
    float asum = red[0];
#pragma unroll
    for (int w = 1; w < 8; w++) asum += red[w];
    __syncthreads();

    v = nd;
#pragma unroll
    for (int o = 16; o > 0; o >>= 1) v = fmaxf(v, __shfl_xor_sync(0xffffffffu, v, o));
    if (lane == 0) red[warp] = v;
    __syncthreads();
    float m = red[0];
#pragma unroll
    for (int w = 1; w < 8; w++) m = fmaxf(m, red[w]);
    __syncthreads();

    const float e = mj ? expf(nd - m) : 0.f;
    v = e;
#pragma unroll
    for (int o = 16; o > 0; o >>= 1) v += __shfl_xor_sync(0xffffffffu, v, o);
    if (lane == 0) red[warp] = v;
    __syncthreads();
    float esum = red[0];
#pragma unroll
    for (int w = 1; w < 8; w++) esum += red[w];

    g_pd[(size_t)bi*PN + j] = LAM_ADJ_C * a / (asum + 1e-6f) + LAM_DIST * (e / esum);
}

// ---------------------------------------------------------------------------
// mma attention: one CTA per (b, h, 128-q half)
// smem: Qh|Ql (32KB) | Kh|Kl -> Vh|Vl (64KB) | S/P (130KB, stride 1040B) | pen (1KB)
// S row r (fp32, 1024B used) is overwritten in place by P row r = [hi 512B | lo 512B]
// ---------------------------------------------------------------------------
#define SQ_OFF   0
#define SK_OFF   32768
#define SS_OFF   98304
#define SROWB    1040
#define SPEN_OFF (SS_OFF + 128*SROWB)      // 231424
#define ATT_DYN  (SPEN_OFF + 1024)         // 232448

__global__ __launch_bounds__(256, 1)
void attn_mma_kernel(const int* __restrict__ mask)
{
    extern __shared__ char dsm[];
    const uint32_t sb = smem_u32(dsm);
    const int tid = threadIdx.x;
    const int wid = tid >> 5, lane = tid & 31;
    const int b = blockIdx.z, h = blockIdx.y;
    const int q0 = blockIdx.x * 128;
    const int bh = b * PH + h;

    const size_t head = (size_t)bh * PN * PDK;
    const __nv_bfloat16* Qh = g_qh + head + (size_t)q0 * PDK;
    const __nv_bfloat16* Ql = g_ql + head + (size_t)q0 * PDK;

    // stage Q (128x64) and K (256x64), both hi/lo, swizzled 128B rows
    for (int i = tid; i < 1024; i += 256) {
        const int row = i >> 3, s = i & 7;
        const uint32_t d = (uint32_t)(row * 128 + ((s ^ (row & 7)) << 4));
        cp16(sb + SQ_OFF + d,         Qh + row * 64 + s * 8);
        cp16(sb + SQ_OFF + 16384 + d, Ql + row * 64 + s * 8);
    }
    for (int i = tid; i < 2048; i += 256) {
        const int row = i >> 3, s = i & 7;
        const uint32_t d = (uint32_t)(row * 128 + ((s ^ (row & 7)) << 4));
        cp16(sb + SK_OFF + d,         g_kh + head + row * 64 + s * 8);
        cp16(sb + SK_OFF + 32768 + d, g_kl + head + row * 64 + s * 8);
    }
    CP_COMMIT();
    sts32f(sb + SPEN_OFF + tid * 4, mask[(b << 8) + tid] ? 0.f : -1e12f);
    CP_WAIT0();
    __syncthreads();

    // ---------------- phase A: S = Q @ K^T ----------------
    {
        const int wm = (wid & 1) * 64;
        const int wn = (wid >> 1) * 32;
        const int ag = lane >> 3;
        const int arow = wm + (lane & 7) + 8 * (ag & 1);
        const int aseg0 = ag >> 1;
        const int bg = (lane >> 3) & 1;

        for (int nh = 0; nh < 2; ++nh) {
            float acc[4][4][4];
#pragma unroll
            for (int mt = 0; mt < 4; mt++)
#pragma unroll
                for (int nt = 0; nt < 4; nt++)
#pragma unroll
                    for (int r = 0; r < 4; r++) acc[mt][nt][r] = 0.f;

#pragma unroll
            for (int k = 0; k < 4; ++k) {
                uint32_t ahf[4][4], alf[4][4], bhf[4][2], blf[4][2];
#pragma unroll
                for (int mt = 0; mt < 4; mt++) {
                    const int r = arow + mt * 16;
                    const uint32_t ad = sb + SQ_OFF + (uint32_t)(r * 128
                                      + (((2*k + aseg0) ^ (r & 7)) << 4));
                    ldm_x4(ad, ahf[mt]);
                    ldm_x4(ad + 16384, alf[mt]);
                }
#pragma unroll
                for (int nt = 0; nt < 4; nt++) {
                    const int r = nh * 128 + wn + nt * 8 + (lane & 7);
                    const uint32_t bd = sb + SK_OFF + (uint32_t)(r * 128
                                      + (((2*k + bg) ^ (r & 7)) << 4));
                    ldm_x2(bd, bhf[nt]);
                    ldm_x2(bd + 32768, blf[nt]);
                }
#pragma unroll
                for (int mt = 0; mt < 4; mt++)
#pragma unroll
                    for (int nt = 0; nt < 4; nt++) {
                        mma16816(acc[mt][nt], ahf[mt], bhf[nt]);
                        mma16816(acc[mt][nt], ahf[mt], blf[nt]);
                        mma16816(acc[mt][nt], alf[mt], bhf[nt]);
                    }
            }
            // write S (fp32)
            const int g4 = lane >> 2, t4 = lane & 3;
#pragma unroll
            for (int mt = 0; mt < 4; mt++) {
                const int row = wm + mt * 16 + g4;
#pragma unroll
                for (int nt = 0; nt < 4; nt++) {
                    const int col = nh * 128 + wn + nt * 8 + t4 * 2;
                    sts64f(sb + SS_OFF + (uint32_t)(row * SROWB + col * 4),
                           acc[mt][nt][0], acc[mt][nt][1]);
                    sts64f(sb + SS_OFF + (uint32_t)((row + 8) * SROWB + col * 4),
                           acc[mt][nt][2], acc[mt][nt][3]);
                }
            }
        }
    }
    __syncthreads();

    // ---------------- phase B: V staging + softmax + pd -> P (in place) -----
    for (int i = tid; i < 2048; i += 256) {
        const int row = i >> 3, s = i & 7;
        const uint32_t d = (uint32_t)(row * 128 + ((s ^ (row & 7)) << 4));
        cp16(sb + SK_OFF + d,         g_vh + head + row * 64 + s * 8);
        cp16(sb + SK_OFF + 32768 + d, g_vl + head + row * 64 + s * 8);
    }
    CP_COMMIT();

    {
        float pen[8];
#pragma unroll
        for (int i = 0; i < 8; i++)
            pen[i] = lds32f(sb + SPEN_OFF + (lane * 8 + i) * 4);
        const float* pdbase = g_pd + ((size_t)b * PN + q0) * PN;

        for (int r = wid * 16; r < wid * 16 + 16; ++r) {
            const uint32_t rb = sb + SS_OFF + (uint32_t)(r * SROWB) + lane * 32;
            float4 s0 = lds128f(rb);
            float4 s1 = lds128f(rb + 16);
            float v[8];
            v[0] = s0.x*0.125f + pen[0]; v[1] = s0.y*0.125f + pen[1];
            v[2] = s0.z*0.125f + pen[2]; v[3] = s0.w*0.125f + pen[3];
            v[4] = s1.x*0.125f + pen[4]; v[5] = s1.y*0.125f + pen[5];
            v[6] = s1.z*0.125f + pen[6]; v[7] = s1.w*0.125f + pen[7];
            float m = v[0];
#pragma unroll
            for (int i = 1; i < 8; i++) m = fmaxf(m, v[i]);
#pragma unroll
            for (int o = 16; o > 0; o >>= 1) m = fmaxf(m, __shfl_xor_sync(0xffffffffu, m, o));
            float e[8], sum = 0.f;
#pragma unroll
            for (int i = 0; i < 8; i++) { e[i] = __expf(v[i] - m); sum += e[i]; }
#pragma unroll
            for (int o = 16; o > 0; o >>= 1) sum += __shfl_xor_sync(0xffffffffu, sum, o);
            const float scale = LAM_ATT / sum;
            const float4 p0 = *(const float4*)(pdbase + (size_t)r * PN + lane * 8);
            const float4 p1 = *(const float4*)(pdbase + (size_t)r * PN + lane * 8 + 4);
            float p[8];
            p[0] = e[0]*scale + p0.x; p[1] = e[1]*scale + p0.y;
            p[2] = e[2]*scale + p0.z; p[3] = e[3]*scale + p0.w;
            p[4] = e[4]*scale + p1.x; p[5] = e[5]*scale + p1.y;
            p[6] = e[6]*scale + p1.z; p[7] = e[7]*scale + p1.w;
            // split to hi/lo bf16 and write P in place over S row r
            uint32_t hi[4], lo[4];
#pragma unroll
            for (int i = 0; i < 4; i++) {
                const __nv_bfloat16 ha = __float2bfloat16(p[2*i]);
                const __nv_bfloat16 hb = __float2bfloat16(p[2*i+1]);
                hi[i] = bf2_u32(__halves2bfloat162(ha, hb));
                lo[i] = bf2_u32(__halves2bfloat162(
                            __float2bfloat16(p[2*i]   - __bfloat162float(ha)),
                            __float2bfloat16(p[2*i+1] - __bfloat162float(hb))));
            }
            const uint32_t pb = sb + SS_OFF + (uint32_t)(r * SROWB) + lane * 16;
            sts128u(pb,       hi[0], hi[1], hi[2], hi[3]);
            sts128u(pb + 512, lo[0], lo[1], lo[2], lo[3]);
        }
    }
    CP_WAIT0();
    __syncthreads();

    // ---------------- phase C: O = P @ V ----------------
    {
        const int wm = (wid & 1) * 64;
        const int wn = (wid >> 1) * 16;       // dk offset, 4 warps x 16
        const int ag = lane >> 3;
        const int arow = wm + (lane & 7) + 8 * (ag & 1);
        const int aseg0 = ag >> 1;

        float acc[4][2][4];
#pragma unroll
        for (int mt = 0; mt < 4; mt++)
#pragma unroll
            for (int nt = 0; nt < 2; nt++)
#pragma unroll
                for (int r = 0; r < 4; r++) acc[mt][nt][r] = 0.f;

        for (int k = 0; k < 16; ++k) {        // 16 k16 steps over 256 keys
            uint32_t ph[4][4], pl[4][4], vh[2][2], vl[2][2];
#pragma unroll
            for (int mt = 0; mt < 4; mt++) {
                const int r = arow + mt * 16;
                const uint32_t ad = sb + SS_OFF + (uint32_t)(r * SROWB
                                  + (2*k + aseg0) * 16);
                ldm_x4(ad, ph[mt]);
                ldm_x4(ad + 512, pl[mt]);
            }
#pragma unroll
            for (int nt = 0; nt < 2; nt++) {
                const int key = k * 16 + (lane & 15);
                const int ds  = (wn >> 3) + nt;
                const uint32_t vd = sb + SK_OFF + (uint32_t)(key * 128
                                  + ((ds ^ (key & 7)) << 4));
                ldm_x2_t(vd, vh[nt]);
                ldm_x2_t(vd + 32768, vl[nt]);
            }
#pragma unroll
            for (int mt = 0; mt < 4; mt++)
#pragma unroll
                for (int nt = 0; nt < 2; nt++) {
                    mma16816(acc[mt][nt], ph[mt], vh[nt]);
                    mma16816(acc[mt][nt], ph[mt], vl[nt]);
                    mma16816(acc[mt][nt], pl[mt], vh[nt]);
                }
        }

        // epilogue: split fp32 O -> g_xh/g_xl at [b*256+q][h*64+dk]
        const int g4 = lane >> 2, t4 = lane & 3;
#pragma unroll
        for (int mt = 0; mt < 4; mt++) {
#pragma unroll
            for (int nt = 0; nt < 2; nt++) {
                const int colg = h * PDK + wn + nt * 8 + t4 * 2;
#pragma unroll
                for (int half = 0; half < 2; half++) {
                    const int mg = b * PN + q0 + wm + mt * 16 + g4 + half * 8;
                    const float vx = acc[mt][nt][half*2 + 0];
                    const float vy = acc[mt][nt][half*2 + 1];
                    const __nv_bfloat16 hx = __float2bfloat16(vx);
                    const __nv_bfloat16 hy = __float2bfloat16(vy);
                    *(__nv_bfloat162*)(g_xh + (size_t)mg * PD + colg) =
                        __halves2bfloat162(hx, hy);
                    *(__nv_bfloat162*)(g_xl + (size_t)mg * PD + colg) =
                        __halves2bfloat162(__float2bfloat16(vx - __bfloat162float(hx)),
                                           __float2bfloat16(vy - __bfloat162float(hy)));
                }
            }
        }
    }
}

// ---------------------------------------------------------------------------
extern "C" void kernel_launch(void* const* d_in, const int* in_sizes, int n_in,
                              void* d_out, int out_size)
{
    const float* query = (const float*)d_in[0];
    const float* key   = (const float*)d_in[1];
    const float* value = (const float*)d_in[2];
    const float* adj   = (const float*)d_in[3];
    const float* dist  = (const float*)d_in[4];
    const int*   mask  = (const int*)d_in[6];
    const float* Wq = (const float*)d_in[7];
    const float* bq = (const float*)d_in[8];
    const float* Wk = (const float*)d_in[9];
    const float* bk = (const float*)d_in[10];
    const float* Wv = (const float*)d_in[11];
    const float* bv = (const float*)d_in[12];
    const float* Wo = (const float*)d_in[13];
    const float* bo = (const float*)d_in[14];
    float* out = (float*)d_out;

    static bool attr_set = false;
    if (!attr_set) {
        cudaFuncSetAttribute(qkv_mma_kernel, cudaFuncAttributeMaxDynamicSharedMemorySize, GEMM_DYN);
        cudaFuncSetAttribute(out_mma_kernel, cudaFuncAttributeMaxDynamicSharedMemorySize, GEMM_DYN);
        cudaFuncSetAttribute(attn_mma_kernel, cudaFuncAttributeMaxDynamicSharedMemorySize, ATT_DYN);
        attr_set = true;
    }

    split_wt_kernel<<<dim3(32, 32, 4), 256>>>(Wq, Wk, Wv, Wo);
    split_qkv_kernel<<<dim3(GM*PD/4/256, 3), 256>>>(query, key, value);

    qkv_mma_kernel<<<dim3(PD/128, GM/128, 3), 256, GEMM_DYN>>>(bq, bk, bv);

    pd_kernel<<<PB*PN, 256>>>(adj, dist, mask);

    attn_mma_kernel<<<dim3(2, PH, PB), 256, ATT_DYN>>>(mask);

    out_mma_kernel<<<dim3(PD/128, GM/128, 1), 256, GEMM_DYN>>>(bo, out);
}

// round 11
// speedup vs baseline: 3.3055x; 1.1663x over previous
#include <cuda_runtime.h>
#include <cuda_bf16.h>
#include <math_constants.h>
#include <cstdint>

// ---------------- problem constants ----------------
#define PB 16
#define PN 256
#define PD 1024
#define PH 16
#define PDK 64
#define GM (PB*PN)   // 4096

#define LAM_ATT 0.33f
#define LAM_DIST 0.33f
__device__ __constant__ float LAM_ADJ_C = (float)(1.0 - 0.33 - 0.33);

// ---------------- device scratch (no cudaMalloc allowed) ----------------
__device__ float g_pd[PB*PN*PN];      // LAM_DIST*p_dist + LAM_ADJ*p_adj

// split-bf16 operands
__device__ __nv_bfloat16 g_wt_hi[4][PD*PD];   // weights transposed: [n][k]
__device__ __nv_bfloat16 g_wt_lo[4][PD*PD];
__device__ __nv_bfloat16 g_ah[3][GM*PD];      // activations q/k/v: [m][k]
__device__ __nv_bfloat16 g_al[3][GM*PD];
// projected Q/K/V, split bf16, head layout [b][h][n][dk]
__device__ __nv_bfloat16 g_qh[GM*PD]; __device__ __nv_bfloat16 g_ql[GM*PD];
__device__ __nv_bfloat16 g_kh[GM*PD]; __device__ __nv_bfloat16 g_kl[GM*PD];
__device__ __nv_bfloat16 g_vh[GM*PD]; __device__ __nv_bfloat16 g_vl[GM*PD];
// attention output, split bf16, [m][d]
__device__ __nv_bfloat16 g_xh[GM*PD]; __device__ __nv_bfloat16 g_xl[GM*PD];

// ---------------- helpers ----------------
__device__ __forceinline__ uint32_t bf2_u32(__nv_bfloat162 v) {
    union { __nv_bfloat162 b; uint32_t u; } c;
    c.b = v;
    return c.u;
}
__device__ __forceinline__ uint32_t smem_u32(const void* p) {
    uint32_t a;
    asm("{ .reg .u64 t; cvta.to.shared.u64 t, %1; cvt.u32.u64 %0, t; }" : "=r"(a) : "l"(p));
    return a;
}
__device__ __forceinline__ void cp16(uint32_t dst, const void* src) {
    asm volatile("cp.async.cg.shared.global [%0], [%1], 16;" :: "r"(dst), "l"(src) : "memory");
}
#define CP_COMMIT() asm volatile("cp.async.commit_group;" ::: "memory")
#define CP_WAIT0()  asm volatile("cp.async.wait_group 0;" ::: "memory")
#define CP_WAIT1()  asm volatile("cp.async.wait_group 1;" ::: "memory")

__device__ __forceinline__ void ldm_x4(uint32_t a, uint32_t* r) {
    asm volatile("ldmatrix.sync.aligned.m8n8.x4.shared.b16 {%0,%1,%2,%3}, [%4];"
                 : "=r"(r[0]), "=r"(r[1]), "=r"(r[2]), "=r"(r[3]) : "r"(a));
}
__device__ __forceinline__ void ldm_x2(uint32_t a, uint32_t* r) {
    asm volatile("ldmatrix.sync.aligned.m8n8.x2.shared.b16 {%0,%1}, [%2];"
                 : "=r"(r[0]), "=r"(r[1]) : "r"(a));
}
__device__ __forceinline__ void ldm_x2_t(uint32_t a, uint32_t* r) {
    asm volatile("ldmatrix.sync.aligned.m8n8.x2.trans.shared.b16 {%0,%1}, [%2];"
                 : "=r"(r[0]), "=r"(r[1]) : "r"(a));
}
__device__ __forceinline__ void mma16816(float* c, const uint32_t* a, const uint32_t* b) {
    asm volatile("mma.sync.aligned.m16n8k16.row.col.f32.bf16.bf16.f32 "
                 "{%0,%1,%2,%3}, {%4,%5,%6,%7}, {%8,%9}, {%0,%1,%2,%3};"
                 : "+f"(c[0]), "+f"(c[1]), "+f"(c[2]), "+f"(c[3])
                 : "r"(a[0]), "r"(a[1]), "r"(a[2]), "r"(a[3]), "r"(b[0]), "r"(b[1]));
}
__device__ __forceinline__ void sts32f(uint32_t addr, float v) {
    asm volatile("st.shared.f32 [%0], %1;" :: "r"(addr), "f"(v) : "memory");
}
__device__ __forceinline__ float lds32f(uint32_t addr) {
    float v; asm volatile("ld.shared.f32 %0, [%1];" : "=f"(v) : "r"(addr)); return v;
}
__device__ __forceinline__ float4 lds128f(uint32_t addr) {
    float4 v;
    asm volatile("ld.shared.v4.f32 {%0,%1,%2,%3}, [%4];"
                 : "=f"(v.x), "=f"(v.y), "=f"(v.z), "=f"(v.w) : "r"(addr));
    return v;
}
__device__ __forceinline__ void sts128u(uint32_t addr, uint32_t a, uint32_t b, uint32_t c, uint32_t d) {
    asm volatile("st.shared.v4.b32 [%0], {%1,%2,%3,%4};"
                 :: "r"(addr), "r"(a), "r"(b), "r"(c), "r"(d) : "memory");
}
__device__ __forceinline__ void sts64f(uint32_t addr, float a, float b) {
    asm volatile("st.shared.v2.f32 [%0], {%1,%2};" :: "r"(addr), "f"(a), "f"(b) : "memory");
}

// ---------------------------------------------------------------------------
// split/transpose prep kernels
// ---------------------------------------------------------------------------
__global__ __launch_bounds__(256)
void split_wt_kernel(const float* __restrict__ W0, const float* __restrict__ W1,
                     const float* __restrict__ W2, const float* __restrict__ W3)
{
    __shared__ float t[32][33];
    const int z = blockIdx.z;
    const float* W = (z == 0) ? W0 : (z == 1) ? W1 : (z == 2) ? W2 : W3;
    __nv_bfloat16* Hi = g_wt_hi[z];
    __nv_bfloat16* Lo = g_wt_lo[z];
    const int n0 = blockIdx.x * 32, k0 = blockIdx.y * 32;
    const int tx = threadIdx.x & 31, ty = threadIdx.x >> 5;
#pragma unroll
    for (int i = 0; i < 4; i++)
        t[ty + i*8][tx] = W[(size_t)(k0 + ty + i*8) * PD + n0 + tx];
    __syncthreads();
#pragma unroll
    for (int i = 0; i < 4; i++) {
        const int n = n0 + ty + i*8;
        const float v = t[tx][ty + i*8];
        const __nv_bfloat16 h = __float2bfloat16(v);
        Hi[(size_t)n * PD + k0 + tx] = h;
        Lo[(size_t)n * PD + k0 + tx] = __float2bfloat16(v - __bfloat162float(h));
    }
}

__device__ __forceinline__ void split_vec(const float* __restrict__ src,
                                          __nv_bfloat16* __restrict__ hi,
                                          __nv_bfloat16* __restrict__ lo, int i)
{
    const float4 v = ((const float4*)src)[i];
    const __nv_bfloat16 hx = __float2bfloat16(v.x);
    const __nv_bfloat16 hy = __float2bfloat16(v.y);
    const __nv_bfloat16 hz = __float2bfloat16(v.z);
    const __nv_bfloat16 hw = __float2bfloat16(v.w);
    __nv_bfloat162* H = (__nv_bfloat162*)hi;
    __nv_bfloat162* L = (__nv_bfloat162*)lo;
    H[i*2 + 0] = __halves2bfloat162(hx, hy);
    H[i*2 + 1] = __halves2bfloat162(hz, hw);
    L[i*2 + 0] = __halves2bfloat162(__float2bfloat16(v.x - __bfloat162float(hx)),
                                    __float2bfloat16(v.y - __bfloat162float(hy)));
    L[i*2 + 1] = __halves2bfloat162(__float2bfloat16(v.z - __bfloat162float(hz)),
                                    __float2bfloat16(v.w - __bfloat162float(hw)));
}

__global__ __launch_bounds__(256)
void split_qkv_kernel(const float* __restrict__ q, const float* __restrict__ k,
                      const float* __restrict__ v)
{
    const int z = blockIdx.y;
    const float* src = (z == 0) ? q : (z == 1) ? k : v;
    split_vec(src, g_ah[z], g_al[z], blockIdx.x * 256 + threadIdx.x);
}

// ---------------------------------------------------------------------------
// mma.sync split-bf16 GEMM (CTA 128x128, KC=32, 3-stage cp.async pipeline)
// out_mode 0: fp32 row-major [m][n]
// out_mode 1: split bf16 head layout [b][h][n][dk] into (Ch, Cl)
// ---------------------------------------------------------------------------
#define KCH 32
#define NCHUNK (PD / KCH)
#define VOFF 8192
#define BUFOFF 32768
#define GEMM_DYN (3 * BUFOFF)     // 98304

__device__ __forceinline__ void stage_chunk(
    uint32_t sb, const __nv_bfloat16* __restrict__ Ah, const __nv_bfloat16* __restrict__ Al,
    const __nv_bfloat16* __restrict__ Bh, const __nv_bfloat16* __restrict__ Bl,
    int m0, int n0, int kt, int tid)
{
#pragma unroll
    for (int i = 0; i < 2; ++i) {
        const int idx = tid + i * 256;
        const int row = idx >> 2;
        const int seg = idx & 3;
        const uint32_t doff = (uint32_t)(row * 64 + ((seg ^ ((row >> 1) & 3)) * 16));
        const size_t aoff = (size_t)(m0 + row) * PD + kt + seg * 8;
        const size_t boff = (size_t)(n0 + row) * PD + kt + seg * 8;
        cp16(sb + 0*VOFF + doff, Ah + aoff);
        cp16(sb + 1*VOFF + doff, Al + aoff);
        cp16(sb + 2*VOFF + doff, Bh + boff);
        cp16(sb + 3*VOFF + doff, Bl + boff);
    }
}

__device__ __forceinline__ void gemm_core(
    const __nv_bfloat16* __restrict__ Ah, const __nv_bfloat16* __restrict__ Al,
    const __nv_bfloat16* __restrict__ Bh, const __nv_bfloat16* __restrict__ Bl,
    const float* __restrict__ bias, float* __restrict__ C,
    __nv_bfloat16* __restrict__ Ch, __nv_bfloat16* __restrict__ Cl, int out_mode)
{
    extern __shared__ char dsm[];
    const uint32_t sb = smem_u32(dsm);
    const int tid  = threadIdx.x;
    const int wid  = tid >> 5;
    const int lane = tid & 31;
    const int m0 = blockIdx.y * 128;
    const int n0 = blockIdx.x * 128;

    const int wm = (wid & 1) * 64;
    const int wn = (wid >> 1) * 32;

    // A ldmatrix.x4 lane mapping (16 rows x k16)
    const int ag   = lane >> 3;
    const int arow = wm + (lane & 7) + 8 * (ag & 1);
    const int aseg = ag >> 1;
    const uint32_t a_off = (uint32_t)(arow * 64 + ((aseg ^ ((arow >> 1) & 3)) * 16));

    // B ldmatrix.x4 lane mapping: one x4 covers two n8 tiles (pair p)
    // matrix g = lane>>3: rowblk = (g>>1), kseg = g&1
    const int bsg  = (lane >> 3) & 1;
    const int brow_in = ((lane >> 4) & 1) * 8 + (lane & 7);
    const int brow0 = wn + brow_in;            // pair 0 (tiles 0,1)
    const int brow1 = wn + 16 + brow_in;       // pair 1 (tiles 2,3)
    const uint32_t b_off0 = (uint32_t)(brow0 * 64 + ((bsg ^ ((brow0 >> 1) & 3)) * 16));
    const uint32_t b_off1 = (uint32_t)(brow1 * 64 + ((bsg ^ ((brow1 >> 1) & 3)) * 16));

    float acc[4][4][4];
#pragma unroll
    for (int mt = 0; mt < 4; mt++)
#pragma unroll
        for (int nt = 0; nt < 4; nt++)
#pragma unroll
            for (int r = 0; r < 4; r++) acc[mt][nt][r] = 0.f;

    stage_chunk(sb + 0*BUFOFF, Ah, Al, Bh, Bl, m0, n0, 0*KCH, tid);
    CP_COMMIT();
    stage_chunk(sb + 1*BUFOFF, Ah, Al, Bh, Bl, m0, n0, 1*KCH, tid);
    CP_COMMIT();

    int bufidx = 0, stageidx = 2;
    for (int c = 0; c < NCHUNK; ++c) {
        if (c + 1 < NCHUNK) { CP_WAIT1(); } else { CP_WAIT0(); }
        __syncthreads();
        if (c + 2 < NCHUNK) {
            stage_chunk(sb + stageidx * BUFOFF, Ah, Al, Bh, Bl, m0, n0, (c + 2) * KCH, tid);
            CP_COMMIT();
            stageidx = (stageidx == 2) ? 0 : stageidx + 1;
        }
        const uint32_t buf = sb + bufidx * BUFOFF;
        bufidx = (bufidx == 2) ? 0 : bufidx + 1;

#pragma unroll
        for (int ks = 0; ks < 2; ++ks) {
            const uint32_t kx = ks * 32;
            uint32_t ah[4][4], al[4][4], bh[4][2], bl[4][2];
#pragma unroll
            for (int mt = 0; mt < 4; mt++)
                ldm_x4(buf + 0*VOFF + mt*1024 + (a_off ^ kx), ah[mt]);
            ldm_x4(buf + 2*VOFF + (b_off0 ^ kx), &bh[0][0]);
            ldm_x4(buf + 2*VOFF + (b_off1 ^ kx), &bh[2][0]);
#pragma unroll
            for (int mt = 0; mt < 4; mt++)
#pragma unroll
                for (int nt = 0; nt < 4; nt++)
                    mma16816(acc[mt][nt], ah[mt], bh[nt]);
#pragma unroll
            for (int mt = 0; mt < 4; mt++)
                ldm_x4(buf + 1*VOFF + mt*1024 + (a_off ^ kx), al[mt]);
#pragma unroll
            for (int mt = 0; mt < 4; mt++)
#pragma unroll
                for (int nt = 0; nt < 4; nt++)
                    mma16816(acc[mt][nt], al[mt], bh[nt]);
            ldm_x4(buf + 3*VOFF + (b_off0 ^ kx), &bl[0][0]);
            ldm_x4(buf + 3*VOFF + (b_off1 ^ kx), &bl[2][0]);
#pragma unroll
            for (int mt = 0; mt < 4; mt++)
#pragma unroll
                for (int nt = 0; nt < 4; nt++)
                    mma16816(acc[mt][nt], ah[mt], bl[nt]);
        }
        __syncthreads();
    }

    const int g4 = lane >> 2;
    const int t4 = lane & 3;
#pragma unroll
    for (int nt = 0; nt < 4; nt++) {
        const int col = n0 + wn + nt * 8 + t4 * 2;
        const float2 bv = *(const float2*)(bias + col);
#pragma unroll
        for (int mt = 0; mt < 4; mt++) {
            const int row = m0 + wm + mt * 16 + g4;
            float2 v0, v1;
            v0.x = acc[mt][nt][0] + bv.x;  v0.y = acc[mt][nt][1] + bv.y;
            v1.x = acc[mt][nt][2] + bv.x;  v1.y = acc[mt][nt][3] + bv.y;
            if (out_mode == 0) {
                *(float2*)(C + (size_t)row * PD + col)       = v0;
                *(float2*)(C + (size_t)(row + 8) * PD + col) = v1;
            } else {
                const int b = row >> 8, h = col >> 6, dk = col & 63;
                const int nn = row & 255;
                const size_t base = (((size_t)(b * PH + h)) * PN + nn) * PDK + dk;
                const __nv_bfloat16 h0x = __float2bfloat16(v0.x);
                const __nv_bfloat16 h0y = __float2bfloat16(v0.y);
                const __nv_bfloat16 h1x = __float2bfloat16(v1.x);
                const __nv_bfloat16 h1y = __float2bfloat16(v1.y);
                *(__nv_bfloat162*)(Ch + base) = __halves2bfloat162(h0x, h0y);
                *(__nv_bfloat162*)(Cl + base) =
                    __halves2bfloat162(__float2bfloat16(v0.x - __bfloat162float(h0x)),
                                       __float2bfloat16(v0.y - __bfloat162float(h0y)));
                *(__nv_bfloat162*)(Ch + base + 8*PDK) = __halves2bfloat162(h1x, h1y);
                *(__nv_bfloat162*)(Cl + base + 8*PDK) =
                    __halves2bfloat162(__float2bfloat16(v1.x - __bfloat162float(h1x)),
                                       __float2bfloat16(v1.y - __bfloat162float(h1y)));
            }
        }
    }
}

__global__ __launch_bounds__(256, 2)
void qkv_mma_kernel(const float* __restrict__ bq, const float* __restrict__ bk,
                    const float* __restrict__ bv)
{
    const int z = blockIdx.z;
    __nv_bfloat16* Ch = (z == 0) ? g_qh : (z == 1) ? g_kh : g_vh;
    __nv_bfloat16* Cl = (z == 0) ? g_ql : (z == 1) ? g_kl : g_vl;
    gemm_core(g_ah[z], g_al[z], g_wt_hi[z], g_wt_lo[z],
              (z == 0) ? bq : (z == 1) ? bk : bv, nullptr, Ch, Cl, 1);
}

__global__ __launch_bounds__(256, 2)
void out_mma_kernel(const float* __restrict__ bo, float* __restrict__ out)
{
    gemm_core(g_xh, g_xl, g_wt_hi[3], g_wt_lo[3], bo, out, nullptr, nullptr, 0);
}

// ---------------------------------------------------------------------------
// pd kernel
// ---------------------------------------------------------------------------
__global__ __launch_bounds__(256)
void pd_kernel(const float* __restrict__ adj, const float* __restrict__ dist,
               const int* __restrict__ mask)
{
    const int bi = blockIdx.x;
    const int b  = bi >> 8;
    const int j  = threadIdx.x;
    const int lane = j & 31, warp = j >> 5;

    const float a  = adj[(size_t)bi*PN + j];
    const int   mj = mask[(b << 8) + j];
    const float nd = mj ? -dist[(size_t)bi*PN + j] : -CUDART_INF_F;

    __shared__ float red[8];

    float v = a;
#pragma unroll
    for (int o = 16; o > 0; o >>= 1) v += __shfl_xor_sync(0xffffffffu, v, o);
    if (lane == 0) red[warp] = v;
    __syncthreads();
    float asum = red[0];
#pragma unroll
    for (int w = 1; w < 8; w++) asum += red[w];
    __syncthreads();

    v = nd;
#pragma unroll
    for (int o = 16; o > 0; o >>= 1) v = fmaxf(v, __shfl_xor_sync(0xffffffffu, v, o));
    if (lane == 0) red[warp] = v;
    __syncthreads();
    float m = red[0];
#pragma unroll
    for (int w = 1; w < 8; w++) m = fmaxf(m, red[w]);
    __syncthreads();

    const float e = mj ? expf(nd - m) : 0.f;
    v = e;
#pragma unroll
    for (int o = 16; o > 0; o >>= 1) v += __shfl_xor_sync(0xffffffffu, v, o);
    if (lane == 0) red[warp] = v;
    __syncthreads();
    float esum = red[0];
#pragma unroll
    for (int w = 1; w < 8; w++) esum += red[w];

    g_pd[(size_t)bi*PN + j] = LAM_ADJ_C * a / (asum + 1e-6f) + LAM_DIST * (e / esum);
}

// ---------------------------------------------------------------------------
// mma attention: one CTA per (b, h, 128-q half)
// smem: Qh|Ql (32KB) | Kh|Kl -> Vh|Vl (64KB) | S/P (130KB, stride 1040B) | pen (1KB)
// S row r (fp32, 1024B used) is overwritten in place by P row r = [hi 512B | lo 512B]
// ---------------------------------------------------------------------------
#define SQ_OFF   0
#define SK_OFF   32768
#define SS_OFF   98304
#define SROWB    1040
#define SPEN_OFF (SS_OFF + 128*SROWB)      // 231424
#define ATT_DYN  (SPEN_OFF + 1024)         // 232448

__global__ __launch_bounds__(256, 1)
void attn_mma_kernel(const int* __restrict__ mask)
{
    extern __shared__ char dsm[];
    const uint32_t sb = smem_u32(dsm);
    const int tid = threadIdx.x;
    const int wid = tid >> 5, lane = tid & 31;
    const int b = blockIdx.z, h = blockIdx.y;
    const int q0 = blockIdx.x * 128;
    const int bh = b * PH + h;

    const size_t head = (size_t)bh * PN * PDK;
    const __nv_bfloat16* Qh = g_qh + head + (size_t)q0 * PDK;
    const __nv_bfloat16* Ql = g_ql + head + (size_t)q0 * PDK;

    // stage Q (128x64) and K (256x64), both hi/lo, swizzled 128B rows
    for (int i = tid; i < 1024; i += 256) {
        const int row = i >> 3, s = i & 7;
        const uint32_t d = (uint32_t)(row * 128 + ((s ^ (row & 7)) << 4));
        cp16(sb + SQ_OFF + d,         Qh + row * 64 + s * 8);
        cp16(sb + SQ_OFF + 16384 + d, Ql + row * 64 + s * 8);
    }
    for (int i = tid; i < 2048; i += 256) {
        const int row = i >> 3, s = i & 7;
        const uint32_t d = (uint32_t)(row * 128 + ((s ^ (row & 7)) << 4));
        cp16(sb + SK_OFF + d,         g_kh + head + row * 64 + s * 8);
        cp16(sb + SK_OFF + 32768 + d, g_kl + head + row * 64 + s * 8);
    }
    CP_COMMIT();
    sts32f(sb + SPEN_OFF + tid * 4, mask[(b << 8) + tid] ? 0.f : -1e12f);
    CP_WAIT0();
    __syncthreads();

    // ---------------- phase A: S = Q @ K^T ----------------
    {
        const int wm = (wid & 1) * 64;
        const int wn = (wid >> 1) * 32;
        const int ag = lane >> 3;
        const int arow = wm + (lane & 7) + 8 * (ag & 1);
        const int aseg0 = ag >> 1;
        const int bg = (lane >> 3) & 1;

        for (int nh = 0; nh < 2; ++nh) {
            float acc[4][4][4];
#pragma unroll
            for (int mt = 0; mt < 4; mt++)
#pragma unroll
                for (int nt = 0; nt < 4; nt++)
#pragma unroll
                    for (int r = 0; r < 4; r++) acc[mt][nt][r] = 0.f;

#pragma unroll
            for (int k = 0; k < 4; ++k) {
                uint32_t ahf[4][4], alf[4][4], bhf[4][2], blf[4][2];
#pragma unroll
                for (int mt = 0; mt < 4; mt++) {
                    const int r = arow + mt * 16;
                    const uint32_t ad = sb + SQ_OFF + (uint32_t)(r * 128
                                      + (((2*k + aseg0) ^ (r & 7)) << 4));
                    ldm_x4(ad, ahf[mt]);
                    ldm_x4(ad + 16384, alf[mt]);
                }
#pragma unroll
                for (int nt = 0; nt < 4; nt++) {
                    const int r = nh * 128 + wn + nt * 8 + (lane & 7);
                    const uint32_t bd = sb + SK_OFF + (uint32_t)(r * 128
                                      + (((2*k + bg) ^ (r & 7)) << 4));
                    ldm_x2(bd, bhf[nt]);
                    ldm_x2(bd + 32768, blf[nt]);
                }
#pragma unroll
                for (int mt = 0; mt < 4; mt++)
#pragma unroll
                    for (int nt = 0; nt < 4; nt++) {
                        mma16816(acc[mt][nt], ahf[mt], bhf[nt]);
                        mma16816(acc[mt][nt], ahf[mt], blf[nt]);
                        mma16816(acc[mt][nt], alf[mt], bhf[nt]);
                    }
            }
            // write S (fp32)
            const int g4 = lane >> 2, t4 = lane & 3;
#pragma unroll
            for (int mt = 0; mt < 4; mt++) {
                const int row = wm + mt * 16 + g4;
#pragma unroll
                for (int nt = 0; nt < 4; nt++) {
                    const int col = nh * 128 + wn + nt * 8 + t4 * 2;
                    sts64f(sb + SS_OFF + (uint32_t)(row * SROWB + col * 4),
                           acc[mt][nt][0], acc[mt][nt][1]);
                    sts64f(sb + SS_OFF + (uint32_t)((row + 8) * SROWB + col * 4),
                           acc[mt][nt][2], acc[mt][nt][3]);
                }
            }
        }
    }
    __syncthreads();

    // ---------------- phase B: V staging + softmax + pd -> P (in place) -----
    for (int i = tid; i < 2048; i += 256) {
        const int row = i >> 3, s = i & 7;
        const uint32_t d = (uint32_t)(row * 128 + ((s ^ (row & 7)) << 4));
        cp16(sb + SK_OFF + d,         g_vh + head + row * 64 + s * 8);
        cp16(sb + SK_OFF + 32768 + d, g_vl + head + row * 64 + s * 8);
    }
    CP_COMMIT();

    {
        float pen[8];
#pragma unroll
        for (int i = 0; i < 8; i++)
            pen[i] = lds32f(sb + SPEN_OFF + (lane * 8 + i) * 4);
        const float* pdbase = g_pd + ((size_t)b * PN + q0) * PN;

        for (int r = wid * 16; r < wid * 16 + 16; ++r) {
            const uint32_t rb = sb + SS_OFF + (uint32_t)(r * SROWB) + lane * 32;
            float4 s0 = lds128f(rb);
            float4 s1 = lds128f(rb + 16);
            float v[8];
            v[0] = s0.x*0.125f + pen[0]; v[1] = s0.y*0.125f + pen[1];
            v[2] = s0.z*0.125f + pen[2]; v[3] = s0.w*0.125f + pen[3];
            v[4] = s1.x*0.125f + pen[4]; v[5] = s1.y*0.125f + pen[5];
            v[6] = s1.z*0.125f + pen[6]; v[7] = s1.w*0.125f + pen[7];
            float m = v[0];
#pragma unroll
            for (int i = 1; i < 8; i++) m = fmaxf(m, v[i]);
#pragma unroll
            for (int o = 16; o > 0; o >>= 1) m = fmaxf(m, __shfl_xor_sync(0xffffffffu, m, o));
            float e[8], sum = 0.f;
#pragma unroll
            for (int i = 0; i < 8; i++) { e[i] = __expf(v[i] - m); sum += e[i]; }
#pragma unroll
            for (int o = 16; o > 0; o >>= 1) sum += __shfl_xor_sync(0xffffffffu, sum, o);
            const float scale = LAM_ATT / sum;
            const float4 p0 = *(const float4*)(pdbase + (size_t)r * PN + lane * 8);
            const float4 p1 = *(const float4*)(pdbase + (size_t)r * PN + lane * 8 + 4);
            float p[8];
            p[0] = e[0]*scale + p0.x; p[1] = e[1]*scale + p0.y;
            p[2] = e[2]*scale + p0.z; p[3] = e[3]*scale + p0.w;
            p[4] = e[4]*scale + p1.x; p[5] = e[5]*scale + p1.y;
            p[6] = e[6]*scale + p1.z; p[7] = e[7]*scale + p1.w;
            // split to hi/lo bf16 and write P in place over S row r
            uint32_t hi[4], lo[4];
#pragma unroll
            for (int i = 0; i < 4; i++) {
                const __nv_bfloat16 ha = __float2bfloat16(p[2*i]);
                const __nv_bfloat16 hb = __float2bfloat16(p[2*i+1]);
                hi[i] = bf2_u32(__halves2bfloat162(ha, hb));
                lo[i] = bf2_u32(__halves2bfloat162(
                            __float2bfloat16(p[2*i]   - __bfloat162float(ha)),
                            __float2bfloat16(p[2*i+1] - __bfloat162float(hb))));
            }
            const uint32_t pb = sb + SS_OFF + (uint32_t)(r * SROWB) + lane * 16;
            sts128u(pb,       hi[0], hi[1], hi[2], hi[3]);
            sts128u(pb + 512, lo[0], lo[1], lo[2], lo[3]);
        }
    }
    CP_WAIT0();
    __syncthreads();

    // ---------------- phase C: O = P @ V ----------------
    {
        const int wm = (wid & 1) * 64;
        const int wn = (wid >> 1) * 16;       // dk offset, 4 warps x 16
        const int ag = lane >> 3;
        const int arow = wm + (lane & 7) + 8 * (ag & 1);
        const int aseg0 = ag >> 1;

        float acc[4][2][4];
#pragma unroll
        for (int mt = 0; mt < 4; mt++)
#pragma unroll
            for (int nt = 0; nt < 2; nt++)
#pragma unroll
                for (int r = 0; r < 4; r++) acc[mt][nt][r] = 0.f;

        for (int k = 0; k < 16; ++k) {        // 16 k16 steps over 256 keys
            uint32_t ph[4][4], pl[4][4], vh[2][2], vl[2][2];
#pragma unroll
            for (int mt = 0; mt < 4; mt++) {
                const int r = arow + mt * 16;
                const uint32_t ad = sb + SS_OFF + (uint32_t)(r * SROWB
                                  + (2*k + aseg0) * 16);
                ldm_x4(ad, ph[mt]);
                ldm_x4(ad + 512, pl[mt]);
            }
#pragma unroll
            for (int nt = 0; nt < 2; nt++) {
                const int key = k * 16 + (lane & 15);
                const int ds  = (wn >> 3) + nt;
                const uint32_t vd = sb + SK_OFF + (uint32_t)(key * 128
                                  + ((ds ^ (key & 7)) << 4));
                ldm_x2_t(vd, vh[nt]);
                ldm_x2_t(vd + 32768, vl[nt]);
            }
#pragma unroll
            for (int mt = 0; mt < 4; mt++)
#pragma unroll
                for (int nt = 0; nt < 2; nt++) {
                    mma16816(acc[mt][nt], ph[mt], vh[nt]);
                    mma16816(acc[mt][nt], ph[mt], vl[nt]);
                    mma16816(acc[mt][nt], pl[mt], vh[nt]);
                }
        }

        // epilogue: split fp32 O -> g_xh/g_xl at [b*256+q][h*64+dk]
        const int g4 = lane >> 2, t4 = lane & 3;
#pragma unroll
        for (int mt = 0; mt < 4; mt++) {
#pragma unroll
            for (int nt = 0; nt < 2; nt++) {
                const int colg = h * PDK + wn + nt * 8 + t4 * 2;
#pragma unroll
                for (int half = 0; half < 2; half++) {
                    const int mg = b * PN + q0 + wm + mt * 16 + g4 + half * 8;
                    const float vx = acc[mt][nt][half*2 + 0];
                    const float vy = acc[mt][nt][half*2 + 1];
                    const __nv_bfloat16 hx = __float2bfloat16(vx);
                    const __nv_bfloat16 hy = __float2bfloat16(vy);
                    *(__nv_bfloat162*)(g_xh + (size_t)mg * PD + colg) =
                        __halves2bfloat162(hx, hy);
                    *(__nv_bfloat162*)(g_xl + (size_t)mg * PD + colg) =
                        __halves2bfloat162(__float2bfloat16(vx - __bfloat162float(hx)),
                                           __float2bfloat16(vy - __bfloat162float(hy)));
                }
            }
        }
    }
}

// ---------------------------------------------------------------------------
extern "C" void kernel_launch(void* const* d_in, const int* in_sizes, int n_in,
                              void* d_out, int out_size)
{
    const float* query = (const float*)d_in[0];
    const float* key   = (const float*)d_in[1];
    const float* value = (const float*)d_in[2];
    const float* adj   = (const float*)d_in[3];
    const float* dist  = (const float*)d_in[4];
    const int*   mask  = (const int*)d_in[6];
    const float* Wq = (const float*)d_in[7];
    const float* bq = (const float*)d_in[8];
    const float* Wk = (const float*)d_in[9];
    const float* bk = (const float*)d_in[10];
    const float* Wv = (const float*)d_in[11];
    const float* bv = (const float*)d_in[12];
    const float* Wo = (const float*)d_in[13];
    const float* bo = (const float*)d_in[14];
    float* out = (float*)d_out;

    static bool attr_set = false;
    if (!attr_set) {
        cudaFuncSetAttribute(qkv_mma_kernel, cudaFuncAttributeMaxDynamicSharedMemorySize, GEMM_DYN);
        cudaFuncSetAttribute(out_mma_kernel, cudaFuncAttributeMaxDynamicSharedMemorySize, GEMM_DYN);
        cudaFuncSetAttribute(attn_mma_kernel, cudaFuncAttributeMaxDynamicSharedMemorySize, ATT_DYN);
        attr_set = true;
    }

    split_wt_kernel<<<dim3(32, 32, 4), 256>>>(Wq, Wk, Wv, Wo);
    split_qkv_kernel<<<dim3(GM*PD/4/256, 3), 256>>>(query, key, value);

    qkv_mma_kernel<<<dim3(PD/128, GM/128, 3), 256, GEMM_DYN>>>(bq, bk, bv);

    pd_kernel<<<PB*PN, 256>>>(adj, dist, mask);

    attn_mma_kernel<<<dim3(2, PH, PB), 256, ATT_DYN>>>(mask);

    out_mma_kernel<<<dim3(PD/128, GM/128, 1), 256, GEMM_DYN>>>(bo, out);
}